// round 1
// baseline (speedup 1.0000x reference)
#include <cuda_runtime.h>
#include <math.h>

// Problem dims
#define BATCH 128
#define SEQ   256
#define NIN   512
#define NH    1024
#define NOUT  512

// GEMM tiling
#define TM 64
#define TN 64
#define TK 16
#define SROW 68   // padded smem row (float4-aligned, low bank conflict)

// Scratch (device globals — no runtime allocation allowed)
__device__ float g_xproj[(size_t)4 * SEQ * BATCH * NH];  // [gate][s][b][h], bias folded in
__device__ float g_pre[4 * BATCH * NH];                  // per-step recurrent GEMM results
__device__ float g_h[BATCH * NH];
__device__ float g_c[BATCH * NH];

struct Ptr4 { const float* p[4]; };

__global__ __launch_bounds__(256) void init_state() {
    int idx = blockIdx.x * 256 + threadIdx.x;   // grid 512 * 256 = 131072 = BATCH*NH
    g_h[idx] = 0.f;
    g_c[idx] = 0.f;
}

// ---------------------------------------------------------------------------
// Input projection: for each gate z: xz[b,s,:] = x[b,s,:] @ Wxz^T + bz
// A = x_seq (M=BATCH*SEQ rows, K=NIN), B = Wxz (NH x NIN row-major) -> C = A B^T
// grid (NH/TN=16, M/TM=512, 4 gates), block 256
// ---------------------------------------------------------------------------
__global__ __launch_bounds__(256) void proj_gemm(const float* __restrict__ X,
                                                 Ptr4 W, Ptr4 Bv) {
    __shared__ float As[TK][SROW];
    __shared__ float Bs[TK][SROW];
    const int gate = blockIdx.z;
    const float* __restrict__ Wm   = W.p[gate];
    const float* __restrict__ bias = Bv.p[gate];
    const int tid = threadIdx.x;
    const int tx = tid & 15, ty = tid >> 4;
    const int mbase = blockIdx.y * TM, nbase = blockIdx.x * TN;
    const int lm = tid >> 2;          // 0..63 (tile row)
    const int lk = (tid & 3) << 2;    // 0,4,8,12 (k chunk)
    float acc[4][4] = {};

    for (int kt = 0; kt < NIN; kt += TK) {
        float4 av = *(const float4*)&X [(size_t)(mbase + lm) * NIN + kt + lk];
        float4 bv = *(const float4*)&Wm[(size_t)(nbase + lm) * NIN + kt + lk];
        __syncthreads();
        As[lk+0][lm] = av.x; As[lk+1][lm] = av.y; As[lk+2][lm] = av.z; As[lk+3][lm] = av.w;
        Bs[lk+0][lm] = bv.x; Bs[lk+1][lm] = bv.y; Bs[lk+2][lm] = bv.z; Bs[lk+3][lm] = bv.w;
        __syncthreads();
        #pragma unroll
        for (int k = 0; k < TK; k++) {
            float4 a = *(const float4*)&As[k][ty << 2];
            float4 b = *(const float4*)&Bs[k][tx << 2];
            float ar[4] = {a.x, a.y, a.z, a.w};
            float br[4] = {b.x, b.y, b.z, b.w};
            #pragma unroll
            for (int i = 0; i < 4; i++)
                #pragma unroll
                for (int j = 0; j < 4; j++)
                    acc[i][j] = fmaf(ar[i], br[j], acc[i][j]);
        }
    }

    #pragma unroll
    for (int i = 0; i < 4; i++) {
        int m = mbase + (ty << 2) + i;      // m = b*SEQ + s
        int bb = m / SEQ, ss = m % SEQ;
        int n0 = nbase + (tx << 2);
        float* dst = &g_xproj[(((size_t)gate * SEQ + ss) * BATCH + bb) * NH + n0];
        #pragma unroll
        for (int j = 0; j < 4; j++) dst[j] = acc[i][j] + bias[n0 + j];
    }
}

// ---------------------------------------------------------------------------
// Recurrent GEMM: pre[gate] = h @ Whz^T   (M=BATCH=128, N=NH, K=NH)
// grid (16, 2, 4) = 128 blocks (one full wave), block 256
// ---------------------------------------------------------------------------
__global__ __launch_bounds__(256) void rec_gemm(Ptr4 Wh) {
    __shared__ float As[TK][SROW];
    __shared__ float Bs[TK][SROW];
    const int gate = blockIdx.z;
    const float* __restrict__ Wm = Wh.p[gate];
    const int tid = threadIdx.x;
    const int tx = tid & 15, ty = tid >> 4;
    const int mbase = blockIdx.y * TM, nbase = blockIdx.x * TN;
    const int lm = tid >> 2;
    const int lk = (tid & 3) << 2;
    float acc[4][4] = {};

    for (int kt = 0; kt < NH; kt += TK) {
        float4 av = *(const float4*)&g_h[(size_t)(mbase + lm) * NH + kt + lk];
        float4 bv = *(const float4*)&Wm [(size_t)(nbase + lm) * NH + kt + lk];
        __syncthreads();
        As[lk+0][lm] = av.x; As[lk+1][lm] = av.y; As[lk+2][lm] = av.z; As[lk+3][lm] = av.w;
        Bs[lk+0][lm] = bv.x; Bs[lk+1][lm] = bv.y; Bs[lk+2][lm] = bv.z; Bs[lk+3][lm] = bv.w;
        __syncthreads();
        #pragma unroll
        for (int k = 0; k < TK; k++) {
            float4 a = *(const float4*)&As[k][ty << 2];
            float4 b = *(const float4*)&Bs[k][tx << 2];
            float ar[4] = {a.x, a.y, a.z, a.w};
            float br[4] = {b.x, b.y, b.z, b.w};
            #pragma unroll
            for (int i = 0; i < 4; i++)
                #pragma unroll
                for (int j = 0; j < 4; j++)
                    acc[i][j] = fmaf(ar[i], br[j], acc[i][j]);
        }
    }

    #pragma unroll
    for (int i = 0; i < 4; i++) {
        int m = mbase + (ty << 2) + i;
        float* dst = &g_pre[(size_t)gate * BATCH * NH + (size_t)m * NH + nbase + (tx << 2)];
        #pragma unroll
        for (int j = 0; j < 4; j++) dst[j] = acc[i][j];
    }
}

// ---------------------------------------------------------------------------
// Elementwise LSTM cell update at timestep t. grid 512 * 256 = BATCH*NH
// ---------------------------------------------------------------------------
__global__ __launch_bounds__(256) void lstm_update(int t) {
    const int idx = blockIdx.x * 256 + threadIdx.x;
    const size_t BH = (size_t)BATCH * NH;
    float pf = g_pre[0 * BH + idx] + g_xproj[((size_t)(0 * SEQ) + t) * BH + idx];
    float pi = g_pre[1 * BH + idx] + g_xproj[((size_t)(1 * SEQ) + t) * BH + idx];
    float pg = g_pre[2 * BH + idx] + g_xproj[((size_t)(2 * SEQ) + t) * BH + idx];
    float po = g_pre[3 * BH + idx] + g_xproj[((size_t)(3 * SEQ) + t) * BH + idx];
    float f  = 1.f / (1.f + expf(-pf));
    float ii = 1.f / (1.f + expf(-pi));
    float g  = tanhf(pg);
    float o  = 1.f / (1.f + expf(-po));
    float c  = f * g_c[idx] + ii * g;
    g_c[idx] = c;
    g_h[idx] = o * tanhf(c);
}

// ---------------------------------------------------------------------------
// Output GEMM: out = h @ Why^T + b   (M=128, N=512, K=1024). grid (8, 2)
// ---------------------------------------------------------------------------
__global__ __launch_bounds__(256) void out_gemm(const float* __restrict__ Wy,
                                                const float* __restrict__ by,
                                                float* __restrict__ out) {
    __shared__ float As[TK][SROW];
    __shared__ float Bs[TK][SROW];
    const int tid = threadIdx.x;
    const int tx = tid & 15, ty = tid >> 4;
    const int mbase = blockIdx.y * TM, nbase = blockIdx.x * TN;
    const int lm = tid >> 2;
    const int lk = (tid & 3) << 2;
    float acc[4][4] = {};

    for (int kt = 0; kt < NH; kt += TK) {
        float4 av = *(const float4*)&g_h[(size_t)(mbase + lm) * NH + kt + lk];
        float4 bv = *(const float4*)&Wy [(size_t)(nbase + lm) * NH + kt + lk];
        __syncthreads();
        As[lk+0][lm] = av.x; As[lk+1][lm] = av.y; As[lk+2][lm] = av.z; As[lk+3][lm] = av.w;
        Bs[lk+0][lm] = bv.x; Bs[lk+1][lm] = bv.y; Bs[lk+2][lm] = bv.z; Bs[lk+3][lm] = bv.w;
        __syncthreads();
        #pragma unroll
        for (int k = 0; k < TK; k++) {
            float4 a = *(const float4*)&As[k][ty << 2];
            float4 b = *(const float4*)&Bs[k][tx << 2];
            float ar[4] = {a.x, a.y, a.z, a.w};
            float br[4] = {b.x, b.y, b.z, b.w};
            #pragma unroll
            for (int i = 0; i < 4; i++)
                #pragma unroll
                for (int j = 0; j < 4; j++)
                    acc[i][j] = fmaf(ar[i], br[j], acc[i][j]);
        }
    }

    #pragma unroll
    for (int i = 0; i < 4; i++) {
        int m = mbase + (ty << 2) + i;
        int n0 = nbase + (tx << 2);
        #pragma unroll
        for (int j = 0; j < 4; j++)
            out[(size_t)m * NOUT + n0 + j] = acc[i][j] + by[n0 + j];
    }
}

// Copy final h and c into d_out after the primary output (out | h | c)
__global__ __launch_bounds__(256) void copy_hc(float* __restrict__ out) {
    const int idx = blockIdx.x * 256 + threadIdx.x;   // 0..131071
    out[(size_t)BATCH * NOUT + idx]                        = g_h[idx];
    out[(size_t)BATCH * NOUT + (size_t)BATCH * NH + idx]   = g_c[idx];
}

// ---------------------------------------------------------------------------
extern "C" void kernel_launch(void* const* d_in, const int* in_sizes, int n_in,
                              void* d_out, int out_size) {
    const float* x_seq = (const float*)d_in[0];
    // gate order: f, i, g, o
    Ptr4 Wx, Bx, Wh;
    Wx.p[0] = (const float*)d_in[1];  Bx.p[0] = (const float*)d_in[2];  Wh.p[0] = (const float*)d_in[3];
    Wx.p[1] = (const float*)d_in[4];  Bx.p[1] = (const float*)d_in[5];  Wh.p[1] = (const float*)d_in[6];
    Wx.p[2] = (const float*)d_in[7];  Bx.p[2] = (const float*)d_in[8];  Wh.p[2] = (const float*)d_in[9];
    Wx.p[3] = (const float*)d_in[10]; Bx.p[3] = (const float*)d_in[11]; Wh.p[3] = (const float*)d_in[12];
    const float* Why_w = (const float*)d_in[13];
    const float* Why_b = (const float*)d_in[14];
    float* out = (float*)d_out;

    init_state<<<512, 256>>>();

    // All-timestep input projections (4 gates fused in grid.z)
    proj_gemm<<<dim3(NH / TN, (BATCH * SEQ) / TM, 4), 256>>>(x_seq, Wx, Bx);

    // Sequential recurrence
    for (int t = 0; t < SEQ; t++) {
        rec_gemm<<<dim3(NH / TN, BATCH / TM, 4), 256>>>(Wh);
        lstm_update<<<512, 256>>>(t);
    }

    // Final projection + state outputs
    out_gemm<<<dim3(NOUT / TN, BATCH / TM), 256>>>(Why_w, Why_b, out);
    copy_hc<<<512, 256>>>(out);
}

// round 4
// speedup vs baseline: 1.5906x; 1.5906x over previous
#include <cuda_runtime.h>
#include <cuda_bf16.h>
#include <mma.h>

using namespace nvcuda;

#define BATCH 128
#define SEQ   256
#define NIN   512
#define NH    1024
#define NOUT  512

typedef __nv_bfloat16 bf16;

// TC GEMM tiling
#define BM 64
#define BN 64
#define BK 32
#define SKS 48   /* smem k-stride in bf16 elements (96 bytes) */

// fp32 out_gemm tiling
#define TM 64
#define TN 64
#define TK 16
#define SROW 68

// ---------------- scratch (device globals) ----------------
__device__ float g_xproj[(size_t)4 * SEQ * BATCH * NH];
__device__ float g_pre[4 * BATCH * NH];
__device__ float g_h[BATCH * NH];
__device__ float g_c[BATCH * NH];
__device__ bf16  g_h_hi[BATCH * NH];
__device__ bf16  g_h_lo[BATCH * NH];
__device__ bf16  g_Wh_hi[(size_t)4 * NH * NH];
__device__ bf16  g_Wh_lo[(size_t)4 * NH * NH];
__device__ bf16  g_Wx_hi[(size_t)4 * NH * NIN];
__device__ bf16  g_Wx_lo[(size_t)4 * NH * NIN];
__device__ bf16  g_x_hi[(size_t)BATCH * SEQ * NIN];
__device__ bf16  g_x_lo[(size_t)BATCH * SEQ * NIN];

struct Ptr4 { const float* p[4]; };

__device__ __forceinline__ float fast_sigmoid(float x) { return 1.f / (1.f + __expf(-x)); }
__device__ __forceinline__ float fast_tanh(float x)    { return 2.f * fast_sigmoid(2.f * x) - 1.f; }

__device__ __forceinline__ bf16* smem_tile(bf16* base, int st, int pl, int row, int col)
{
    return base + ((size_t)((st * 2 + pl) * BM + row)) * SKS + col;
}

// ---------------- init / split kernels ----------------
__global__ __launch_bounds__(256) void init_state()
{
    int idx = blockIdx.x * 256 + threadIdx.x;  // grid 512
    g_h[idx] = 0.f;
    g_c[idx] = 0.f;
    g_h_hi[idx] = __float2bfloat16_rn(0.f);
    g_h_lo[idx] = __float2bfloat16_rn(0.f);
}

__global__ __launch_bounds__(256) void split_wh(Ptr4 W)
{
    size_t idx = (size_t)blockIdx.x * 256 + threadIdx.x;  // 4 * 2^20
    int gate = (int)(idx >> 20);
    float v = W.p[gate][idx & ((1u << 20) - 1)];
    bf16 hv = __float2bfloat16_rn(v);
    g_Wh_hi[idx] = hv;
    g_Wh_lo[idx] = __float2bfloat16_rn(v - __bfloat162float(hv));
}

__global__ __launch_bounds__(256) void split_wx(Ptr4 W)
{
    size_t idx = (size_t)blockIdx.x * 256 + threadIdx.x;  // 4 * 2^19
    int gate = (int)(idx >> 19);
    float v = W.p[gate][idx & ((1u << 19) - 1)];
    bf16 hv = __float2bfloat16_rn(v);
    g_Wx_hi[idx] = hv;
    g_Wx_lo[idx] = __float2bfloat16_rn(v - __bfloat162float(hv));
}

__global__ __launch_bounds__(256) void split_x(const float* __restrict__ x)
{
    size_t idx = (size_t)blockIdx.x * 256 + threadIdx.x;  // 2^24
    float v = x[idx];
    bf16 hv = __float2bfloat16_rn(v);
    g_x_hi[idx] = hv;
    g_x_lo[idx] = __float2bfloat16_rn(v - __bfloat162float(hv));
}

// ---------------- bf16x3 recurrent GEMM (WMMA) ----------------
// g_pre[gate][m][n] = sum_k h[m][k] * Wh[gate][n][k], h = hi + lo, Wh = hi + lo.
// grid (NH/BN=16, BATCH/BM=2, 4); block 256 (8 warps, warp tile 32x16).
__global__ __launch_bounds__(256) void rec_gemm()
{
    __shared__ __align__(16) unsigned char smem_raw[49152];
    bf16* sA = (bf16*)smem_raw;                    // [2][2][BM][SKS]
    bf16* sB = (bf16*)(smem_raw + 24576);          // [2][2][BN][SKS]

    const int gate = blockIdx.z;
    const bf16* __restrict__ Bhi = g_Wh_hi + (size_t)gate * NH * NH;
    const bf16* __restrict__ Blo = g_Wh_lo + (size_t)gate * NH * NH;

    const int tid   = threadIdx.x;
    const int warp  = tid >> 5;
    const int wm    = warp >> 2;
    const int wn    = warp & 3;
    const int mbase = blockIdx.y * BM;
    const int nbase = blockIdx.x * BN;

    const int lr = tid >> 2;
    const int lc = (tid & 3) * 8;

    const bf16* pa_hi = g_h_hi + (size_t)(mbase + lr) * NH + lc;
    const bf16* pa_lo = g_h_lo + (size_t)(mbase + lr) * NH + lc;
    const bf16* pb_hi = Bhi + (size_t)(nbase + lr) * NH + lc;
    const bf16* pb_lo = Blo + (size_t)(nbase + lr) * NH + lc;

    wmma::fragment<wmma::accumulator, 16, 16, 16, float> acc0;
    wmma::fragment<wmma::accumulator, 16, 16, 16, float> acc1;
    wmma::fill_fragment(acc0, 0.0f);
    wmma::fill_fragment(acc1, 0.0f);

    const int NC = NH / BK;   // 32

    uint4 ra_h = *(const uint4*)pa_hi;
    uint4 ra_l = *(const uint4*)pa_lo;
    uint4 rb_h = *(const uint4*)pb_hi;
    uint4 rb_l = *(const uint4*)pb_lo;
    *(uint4*)smem_tile(sA, 0, 0, lr, lc) = ra_h;
    *(uint4*)smem_tile(sA, 0, 1, lr, lc) = ra_l;
    *(uint4*)smem_tile(sB, 0, 0, lr, lc) = rb_h;
    *(uint4*)smem_tile(sB, 0, 1, lr, lc) = rb_l;
    __syncthreads();

    for (int c = 0; c < NC; c++) {
        const int st = c & 1;
        if (c + 1 < NC) {
            const int ko = (c + 1) * BK;
            ra_h = *(const uint4*)(pa_hi + ko);
            ra_l = *(const uint4*)(pa_lo + ko);
            rb_h = *(const uint4*)(pb_hi + ko);
            rb_l = *(const uint4*)(pb_lo + ko);
        }
        #pragma unroll
        for (int ks = 0; ks < 2; ks++) {
            wmma::fragment<wmma::matrix_b, 16, 16, 16, bf16, wmma::col_major> fbh;
            wmma::fragment<wmma::matrix_b, 16, 16, 16, bf16, wmma::col_major> fbl;
            wmma::load_matrix_sync(fbh, smem_tile(sB, st, 0, wn * 16, ks * 16), SKS);
            wmma::load_matrix_sync(fbl, smem_tile(sB, st, 1, wn * 16, ks * 16), SKS);

            wmma::fragment<wmma::matrix_a, 16, 16, 16, bf16, wmma::row_major> fah;
            wmma::fragment<wmma::matrix_a, 16, 16, 16, bf16, wmma::row_major> fal;
            wmma::load_matrix_sync(fah, smem_tile(sA, st, 0, wm * 32, ks * 16), SKS);
            wmma::load_matrix_sync(fal, smem_tile(sA, st, 1, wm * 32, ks * 16), SKS);
            wmma::mma_sync(acc0, fah, fbh, acc0);
            wmma::mma_sync(acc0, fah, fbl, acc0);
            wmma::mma_sync(acc0, fal, fbh, acc0);

            wmma::load_matrix_sync(fah, smem_tile(sA, st, 0, wm * 32 + 16, ks * 16), SKS);
            wmma::load_matrix_sync(fal, smem_tile(sA, st, 1, wm * 32 + 16, ks * 16), SKS);
            wmma::mma_sync(acc1, fah, fbh, acc1);
            wmma::mma_sync(acc1, fah, fbl, acc1);
            wmma::mma_sync(acc1, fal, fbh, acc1);
        }
        if (c + 1 < NC) {
            const int st2 = st ^ 1;
            *(uint4*)smem_tile(sA, st2, 0, lr, lc) = ra_h;
            *(uint4*)smem_tile(sA, st2, 1, lr, lc) = ra_l;
            *(uint4*)smem_tile(sB, st2, 0, lr, lc) = rb_h;
            *(uint4*)smem_tile(sB, st2, 1, lr, lc) = rb_l;
            __syncthreads();
        }
    }

    float* dst0 = g_pre + (size_t)gate * BATCH * NH
                + (size_t)(mbase + wm * 32) * NH + nbase + wn * 16;
    float* dst1 = g_pre + (size_t)gate * BATCH * NH
                + (size_t)(mbase + wm * 32 + 16) * NH + nbase + wn * 16;
    wmma::store_matrix_sync(dst0, acc0, NH, wmma::mem_row_major);
    wmma::store_matrix_sync(dst1, acc1, NH, wmma::mem_row_major);
}

// ---------------- bf16x3 input-projection GEMM (WMMA) ----------------
// g_xproj[gate][s][b][n] = sum_k x[m][k] * Wx[gate][n][k] + bias[n], m = b*SEQ+s.
// grid (NH/BN=16, BATCH*SEQ/BM=512, 4); block 256.
__global__ __launch_bounds__(256) void proj_gemm(Ptr4 Bias)
{
    __shared__ __align__(16) unsigned char smem_raw[49152];
    bf16* sA = (bf16*)smem_raw;
    bf16* sB = (bf16*)(smem_raw + 24576);

    const int gate = blockIdx.z;
    const bf16* __restrict__ Bhi = g_Wx_hi + (size_t)gate * NH * NIN;
    const bf16* __restrict__ Blo = g_Wx_lo + (size_t)gate * NH * NIN;
    const float* __restrict__ bias = Bias.p[gate];

    const int tid   = threadIdx.x;
    const int warp  = tid >> 5;
    const int wm    = warp >> 2;
    const int wn    = warp & 3;
    const int mbase = blockIdx.y * BM;
    const int nbase = blockIdx.x * BN;

    const int lr = tid >> 2;
    const int lc = (tid & 3) * 8;

    const bf16* pa_hi = g_x_hi + (size_t)(mbase + lr) * NIN + lc;
    const bf16* pa_lo = g_x_lo + (size_t)(mbase + lr) * NIN + lc;
    const bf16* pb_hi = Bhi + (size_t)(nbase + lr) * NIN + lc;
    const bf16* pb_lo = Blo + (size_t)(nbase + lr) * NIN + lc;

    wmma::fragment<wmma::accumulator, 16, 16, 16, float> acc0;
    wmma::fragment<wmma::accumulator, 16, 16, 16, float> acc1;
    wmma::fill_fragment(acc0, 0.0f);
    wmma::fill_fragment(acc1, 0.0f);

    const int NC = NIN / BK;   // 16

    uint4 ra_h = *(const uint4*)pa_hi;
    uint4 ra_l = *(const uint4*)pa_lo;
    uint4 rb_h = *(const uint4*)pb_hi;
    uint4 rb_l = *(const uint4*)pb_lo;
    *(uint4*)smem_tile(sA, 0, 0, lr, lc) = ra_h;
    *(uint4*)smem_tile(sA, 0, 1, lr, lc) = ra_l;
    *(uint4*)smem_tile(sB, 0, 0, lr, lc) = rb_h;
    *(uint4*)smem_tile(sB, 0, 1, lr, lc) = rb_l;
    __syncthreads();

    for (int c = 0; c < NC; c++) {
        const int st = c & 1;
        if (c + 1 < NC) {
            const int ko = (c + 1) * BK;
            ra_h = *(const uint4*)(pa_hi + ko);
            ra_l = *(const uint4*)(pa_lo + ko);
            rb_h = *(const uint4*)(pb_hi + ko);
            rb_l = *(const uint4*)(pb_lo + ko);
        }
        #pragma unroll
        for (int ks = 0; ks < 2; ks++) {
            wmma::fragment<wmma::matrix_b, 16, 16, 16, bf16, wmma::col_major> fbh;
            wmma::fragment<wmma::matrix_b, 16, 16, 16, bf16, wmma::col_major> fbl;
            wmma::load_matrix_sync(fbh, smem_tile(sB, st, 0, wn * 16, ks * 16), SKS);
            wmma::load_matrix_sync(fbl, smem_tile(sB, st, 1, wn * 16, ks * 16), SKS);

            wmma::fragment<wmma::matrix_a, 16, 16, 16, bf16, wmma::row_major> fah;
            wmma::fragment<wmma::matrix_a, 16, 16, 16, bf16, wmma::row_major> fal;
            wmma::load_matrix_sync(fah, smem_tile(sA, st, 0, wm * 32, ks * 16), SKS);
            wmma::load_matrix_sync(fal, smem_tile(sA, st, 1, wm * 32, ks * 16), SKS);
            wmma::mma_sync(acc0, fah, fbh, acc0);
            wmma::mma_sync(acc0, fah, fbl, acc0);
            wmma::mma_sync(acc0, fal, fbh, acc0);

            wmma::load_matrix_sync(fah, smem_tile(sA, st, 0, wm * 32 + 16, ks * 16), SKS);
            wmma::load_matrix_sync(fal, smem_tile(sA, st, 1, wm * 32 + 16, ks * 16), SKS);
            wmma::mma_sync(acc1, fah, fbh, acc1);
            wmma::mma_sync(acc1, fah, fbl, acc1);
            wmma::mma_sync(acc1, fal, fbh, acc1);
        }
        if (c + 1 < NC) {
            const int st2 = st ^ 1;
            *(uint4*)smem_tile(sA, st2, 0, lr, lc) = ra_h;
            *(uint4*)smem_tile(sA, st2, 1, lr, lc) = ra_l;
            *(uint4*)smem_tile(sB, st2, 0, lr, lc) = rb_h;
            *(uint4*)smem_tile(sB, st2, 1, lr, lc) = rb_l;
            __syncthreads();
        }
    }

    // stage accumulators in smem, then permuted + biased write to g_xproj
    __syncthreads();
    float* stage = (float*)smem_raw;   // 64 x 64 floats = 16 KB
    wmma::store_matrix_sync(stage + (wm * 32) * 64 + wn * 16, acc0, 64, wmma::mem_row_major);
    wmma::store_matrix_sync(stage + (wm * 32 + 16) * 64 + wn * 16, acc1, 64, wmma::mem_row_major);
    __syncthreads();

    #pragma unroll
    for (int i = 0; i < 4; i++) {
        int e   = tid + i * 256;        // 1024 groups of 4 floats
        int row = e >> 4;
        int c4  = (e & 15) * 4;
        int m   = mbase + row;
        int bb  = m >> 8;               // m = b*SEQ + s, SEQ = 256
        int ss  = m & 255;
        int col = nbase + c4;
        float4 v = *(float4*)(stage + row * 64 + c4);
        v.x += bias[col + 0];
        v.y += bias[col + 1];
        v.z += bias[col + 2];
        v.w += bias[col + 3];
        *(float4*)&g_xproj[(((size_t)gate * SEQ + ss) * BATCH + bb) * NH + col] = v;
    }
}

// ---------------- fused elementwise LSTM cell update ----------------
__device__ __forceinline__ void ld4(float* d, const float* p)
{
    float4 v = *(const float4*)p;
    d[0] = v.x; d[1] = v.y; d[2] = v.z; d[3] = v.w;
}

__global__ __launch_bounds__(256) void lstm_update(int t)
{
    const int i4 = blockIdx.x * 256 + threadIdx.x;  // grid 128 -> 32768 threads
    const size_t BH = (size_t)BATCH * NH;
    const size_t o = (size_t)i4 * 4;

    float pf[4]; float pi4[4]; float pg[4]; float po[4];
    float xf[4]; float xi4[4]; float xg[4]; float xo[4];
    float cv[4]; float hv[4]; float cn[4];

    ld4(pf,  g_pre + 0 * BH + o);
    ld4(pi4, g_pre + 1 * BH + o);
    ld4(pg,  g_pre + 2 * BH + o);
    ld4(po,  g_pre + 3 * BH + o);
    ld4(xf,  g_xproj + ((size_t)(0 * SEQ) + t) * BH + o);
    ld4(xi4, g_xproj + ((size_t)(1 * SEQ) + t) * BH + o);
    ld4(xg,  g_xproj + ((size_t)(2 * SEQ) + t) * BH + o);
    ld4(xo,  g_xproj + ((size_t)(3 * SEQ) + t) * BH + o);
    ld4(cv,  g_c + o);

    #pragma unroll
    for (int j = 0; j < 4; j++) {
        float fg = fast_sigmoid(pf[j] + xf[j]);
        float ig = fast_sigmoid(pi4[j] + xi4[j]);
        float gg = fast_tanh(pg[j] + xg[j]);
        float og = fast_sigmoid(po[j] + xo[j]);
        float c2 = fg * cv[j] + ig * gg;
        cn[j] = c2;
        hv[j] = og * fast_tanh(c2);
    }

    *(float4*)(g_c + o) = make_float4(cn[0], cn[1], cn[2], cn[3]);
    *(float4*)(g_h + o) = make_float4(hv[0], hv[1], hv[2], hv[3]);

    __nv_bfloat162* Hh = (__nv_bfloat162*)g_h_hi;
    __nv_bfloat162* Hl = (__nv_bfloat162*)g_h_lo;
    #pragma unroll
    for (int j = 0; j < 2; j++) {
        __nv_bfloat162 hh = __floats2bfloat162_rn(hv[2 * j], hv[2 * j + 1]);
        float l0 = hv[2 * j]     - __bfloat162float(__low2bfloat16(hh));
        float l1 = hv[2 * j + 1] - __bfloat162float(__high2bfloat16(hh));
        Hh[i4 * 2 + j] = hh;
        Hl[i4 * 2 + j] = __floats2bfloat162_rn(l0, l1);
    }
}

// ---------------- fp32 output GEMM (small) ----------------
__global__ __launch_bounds__(256) void out_gemm(const float* __restrict__ Wy,
                                                const float* __restrict__ by,
                                                float* __restrict__ out)
{
    __shared__ float As[TK][SROW];
    __shared__ float Bs[TK][SROW];
    const int tid = threadIdx.x;
    const int tx = tid & 15;
    const int ty = tid >> 4;
    const int mbase = blockIdx.y * TM;
    const int nbase = blockIdx.x * TN;
    const int lm = tid >> 2;
    const int lk = (tid & 3) << 2;

    float acc[4][4];
    #pragma unroll
    for (int i = 0; i < 4; i++) {
        #pragma unroll
        for (int j = 0; j < 4; j++) { acc[i][j] = 0.f; }
    }

    for (int kt = 0; kt < NH; kt += TK) {
        float4 av = *(const float4*)&g_h[(size_t)(mbase + lm) * NH + kt + lk];
        float4 bv = *(const float4*)&Wy [(size_t)(nbase + lm) * NH + kt + lk];
        __syncthreads();
        As[lk + 0][lm] = av.x; As[lk + 1][lm] = av.y;
        As[lk + 2][lm] = av.z; As[lk + 3][lm] = av.w;
        Bs[lk + 0][lm] = bv.x; Bs[lk + 1][lm] = bv.y;
        Bs[lk + 2][lm] = bv.z; Bs[lk + 3][lm] = bv.w;
        __syncthreads();
        #pragma unroll
        for (int k = 0; k < TK; k++) {
            float ar[4]; float br[4];
            #pragma unroll
            for (int i = 0; i < 4; i++) { ar[i] = As[k][(ty << 2) + i]; }
            #pragma unroll
            for (int j = 0; j < 4; j++) { br[j] = Bs[k][(tx << 2) + j]; }
            #pragma unroll
            for (int i = 0; i < 4; i++) {
                #pragma unroll
                for (int j = 0; j < 4; j++) { acc[i][j] = fmaf(ar[i], br[j], acc[i][j]); }
            }
        }
    }

    #pragma unroll
    for (int i = 0; i < 4; i++) {
        int m = mbase + (ty << 2) + i;
        int n0 = nbase + (tx << 2);
        #pragma unroll
        for (int j = 0; j < 4; j++) {
            out[(size_t)m * NOUT + n0 + j] = acc[i][j] + by[n0 + j];
        }
    }
}

__global__ __launch_bounds__(256) void copy_hc(float* __restrict__ out)
{
    const int idx = blockIdx.x * 256 + threadIdx.x;  // grid 512
    out[(size_t)BATCH * NOUT + idx]                      = g_h[idx];
    out[(size_t)BATCH * NOUT + (size_t)BATCH * NH + idx] = g_c[idx];
}

// ---------------------------------------------------------------------------
extern "C" void kernel_launch(void* const* d_in, const int* in_sizes, int n_in,
                              void* d_out, int out_size)
{
    const float* x_seq = (const float*)d_in[0];
    Ptr4 Wx; Ptr4 Bx; Ptr4 Wh;
    Wx.p[0] = (const float*)d_in[1];  Bx.p[0] = (const float*)d_in[2];  Wh.p[0] = (const float*)d_in[3];
    Wx.p[1] = (const float*)d_in[4];  Bx.p[1] = (const float*)d_in[5];  Wh.p[1] = (const float*)d_in[6];
    Wx.p[2] = (const float*)d_in[7];  Bx.p[2] = (const float*)d_in[8];  Wh.p[2] = (const float*)d_in[9];
    Wx.p[3] = (const float*)d_in[10]; Bx.p[3] = (const float*)d_in[11]; Wh.p[3] = (const float*)d_in[12];
    const float* Why_w = (const float*)d_in[13];
    const float* Why_b = (const float*)d_in[14];
    float* out = (float*)d_out;

    init_state<<<512, 256>>>();

    split_wh<<<(4 * NH * NH) / 256, 256>>>(Wh);
    split_wx<<<(4 * NH * NIN) / 256, 256>>>(Wx);
    split_x<<<(BATCH * SEQ * NIN) / 256, 256>>>(x_seq);

    proj_gemm<<<dim3(NH / BN, (BATCH * SEQ) / BM, 4), 256>>>(Bx);

    for (int t = 0; t < SEQ; t++) {
        rec_gemm<<<dim3(NH / BN, BATCH / BM, 4), 256>>>();
        lstm_update<<<128, 256>>>(t);
    }

    out_gemm<<<dim3(NOUT / TN, BATCH / TM), 256>>>(Why_w, Why_b, out);
    copy_hc<<<512, 256>>>(out);
}

// round 5
// speedup vs baseline: 1.6400x; 1.0311x over previous
#include <cuda_runtime.h>
#include <cuda_bf16.h>
#include <mma.h>

using namespace nvcuda;

#define BATCH 128
#define SEQ   256
#define NIN   512
#define NH    1024
#define NOUT  512

typedef __nv_bfloat16 bf16;

// proj GEMM tiling (unchanged from R4)
#define BM 64
#define BN 64
#define BK 32
#define SKS 48

// fused rec-step tiling
#define FBM 32
#define FBN 32
#define FBK 32
#define FSK 40   /* 80-byte rows: conflict-free ldmatrix */

// fp32 out_gemm tiling
#define TM 64
#define TN 64
#define TK 16
#define SROW 68

// ---------------- scratch (device globals) ----------------
__device__ float g_xproj[(size_t)4 * SEQ * BATCH * NH];
__device__ float g_h[BATCH * NH];
__device__ float g_c[BATCH * NH];
__device__ bf16  g_hA_hi[BATCH * NH];
__device__ bf16  g_hA_lo[BATCH * NH];
__device__ bf16  g_hB_hi[BATCH * NH];
__device__ bf16  g_hB_lo[BATCH * NH];
__device__ bf16  g_Wh_hi[(size_t)4 * NH * NH];
__device__ bf16  g_Wh_lo[(size_t)4 * NH * NH];
__device__ bf16  g_Wx_hi[(size_t)4 * NH * NIN];
__device__ bf16  g_Wx_lo[(size_t)4 * NH * NIN];
__device__ bf16  g_x_hi[(size_t)BATCH * SEQ * NIN];
__device__ bf16  g_x_lo[(size_t)BATCH * SEQ * NIN];

struct Ptr4 { const float* p[4]; };

__device__ __forceinline__ float fast_sigmoid(float x) { return 1.f / (1.f + __expf(-x)); }
__device__ __forceinline__ float fast_tanh(float x)    { return 2.f * fast_sigmoid(2.f * x) - 1.f; }

__device__ __forceinline__ bf16* smem_tile(bf16* base, int st, int pl, int row, int col)
{
    return base + ((size_t)((st * 2 + pl) * BM + row)) * SKS + col;
}

// ---------------- init / split kernels ----------------
__global__ __launch_bounds__(256) void init_state()
{
    int idx = blockIdx.x * 256 + threadIdx.x;  // grid 512
    g_h[idx] = 0.f;
    g_c[idx] = 0.f;
    g_hA_hi[idx] = __float2bfloat16_rn(0.f);
    g_hA_lo[idx] = __float2bfloat16_rn(0.f);
}

__global__ __launch_bounds__(256) void split_wh(Ptr4 W)
{
    size_t idx = (size_t)blockIdx.x * 256 + threadIdx.x;  // 4 * 2^20
    int gate = (int)(idx >> 20);
    float v = W.p[gate][idx & ((1u << 20) - 1)];
    bf16 hv = __float2bfloat16_rn(v);
    g_Wh_hi[idx] = hv;
    g_Wh_lo[idx] = __float2bfloat16_rn(v - __bfloat162float(hv));
}

__global__ __launch_bounds__(256) void split_wx(Ptr4 W)
{
    size_t idx = (size_t)blockIdx.x * 256 + threadIdx.x;  // 4 * 2^19
    int gate = (int)(idx >> 19);
    float v = W.p[gate][idx & ((1u << 19) - 1)];
    bf16 hv = __float2bfloat16_rn(v);
    g_Wx_hi[idx] = hv;
    g_Wx_lo[idx] = __float2bfloat16_rn(v - __bfloat162float(hv));
}

__global__ __launch_bounds__(256) void split_x(const float* __restrict__ x)
{
    size_t idx = (size_t)blockIdx.x * 256 + threadIdx.x;  // 2^24
    float v = x[idx];
    bf16 hv = __float2bfloat16_rn(v);
    g_x_hi[idx] = hv;
    g_x_lo[idx] = __float2bfloat16_rn(v - __bfloat162float(hv));
}

// ---------------- fused recurrent step ----------------
// One launch per timestep. grid (NH/FBN=32, BATCH/FBM=4) = 128 blocks, 256 thr.
// Each block computes pre-activations for ALL 4 gates on its 32x32 (m,n) tile
// via bf16x3 WMMA, then applies the LSTM cell update in the epilogue.
// h is double-buffered (A/B by t parity) to avoid intra-launch races.
__global__ __launch_bounds__(256) void rec_step(int t)
{
    // plane buffer: 10 planes x 32 rows x FSK bf16 = 25600 B
    __shared__ __align__(16) bf16  splanes[10 * FBM * FSK];
    __shared__ __align__(16) float stage[4][FBM][FBN];   // 16 KB

    const int par = t & 1;
    const bf16* __restrict__ hin_hi = par ? g_hB_hi : g_hA_hi;
    const bf16* __restrict__ hin_lo = par ? g_hB_lo : g_hA_lo;
    bf16* __restrict__ hout_hi = par ? g_hA_hi : g_hB_hi;
    bf16* __restrict__ hout_lo = par ? g_hA_lo : g_hB_lo;

    const int tid   = threadIdx.x;
    const int nbase = blockIdx.x * FBN;
    const int mbase = blockIdx.y * FBM;

    // loader setup: 1280 uint4 per stage, 5 per thread
    const bf16* gsrc[5];
    bf16* sdst[5];
    #pragma unroll
    for (int l = 0; l < 5; l++) {
        int idx = l * 256 + tid;
        int p   = idx >> 7;          // plane 0..9
        int w   = idx & 127;
        int row = w >> 2;
        int q   = (w & 3) * 8;
        sdst[l] = splanes + ((size_t)(p * FBM + row)) * FSK + q;
        if (p == 0) {
            gsrc[l] = hin_hi + (size_t)(mbase + row) * NH + q;
        } else if (p == 1) {
            gsrc[l] = hin_lo + (size_t)(mbase + row) * NH + q;
        } else {
            int g2   = p - 2;
            int gate = g2 >> 1;
            int islo = g2 & 1;
            const bf16* wbase = islo ? g_Wh_lo : g_Wh_hi;
            gsrc[l] = wbase + (size_t)gate * NH * NH + (size_t)(nbase + row) * NH + q;
        }
    }

    // warp mapping: wm in 0..1 (16 m-rows), wn in 0..1 (16 n-cols), gp in 0..1
    const int warp = tid >> 5;
    const int wm = (warp >> 2) & 1;
    const int wn = (warp >> 1) & 1;
    const int gp = warp & 1;

    wmma::fragment<wmma::accumulator, 16, 16, 16, float> acc0;
    wmma::fragment<wmma::accumulator, 16, 16, 16, float> acc1;
    wmma::fill_fragment(acc0, 0.0f);
    wmma::fill_fragment(acc1, 0.0f);

    const int NC = NH / FBK;   // 32
    uint4 r0; uint4 r1; uint4 r2; uint4 r3; uint4 r4;
    r0 = *(const uint4*)gsrc[0];
    r1 = *(const uint4*)gsrc[1];
    r2 = *(const uint4*)gsrc[2];
    r3 = *(const uint4*)gsrc[3];
    r4 = *(const uint4*)gsrc[4];

    for (int c = 0; c < NC; c++) {
        __syncthreads();   // previous compute done
        *(uint4*)sdst[0] = r0;
        *(uint4*)sdst[1] = r1;
        *(uint4*)sdst[2] = r2;
        *(uint4*)sdst[3] = r3;
        *(uint4*)sdst[4] = r4;
        __syncthreads();   // stage ready
        if (c + 1 < NC) {
            const int ko = (c + 1) * FBK;
            r0 = *(const uint4*)(gsrc[0] + ko);
            r1 = *(const uint4*)(gsrc[1] + ko);
            r2 = *(const uint4*)(gsrc[2] + ko);
            r3 = *(const uint4*)(gsrc[3] + ko);
            r4 = *(const uint4*)(gsrc[4] + ko);
        }
        #pragma unroll
        for (int ks = 0; ks < 2; ks++) {
            wmma::fragment<wmma::matrix_a, 16, 16, 16, bf16, wmma::row_major> fah;
            wmma::fragment<wmma::matrix_a, 16, 16, 16, bf16, wmma::row_major> fal;
            wmma::load_matrix_sync(fah,
                splanes + ((size_t)(0 * FBM + wm * 16)) * FSK + ks * 16, FSK);
            wmma::load_matrix_sync(fal,
                splanes + ((size_t)(1 * FBM + wm * 16)) * FSK + ks * 16, FSK);

            const int gate0 = gp * 2;
            wmma::fragment<wmma::matrix_b, 16, 16, 16, bf16, wmma::col_major> fbh;
            wmma::fragment<wmma::matrix_b, 16, 16, 16, bf16, wmma::col_major> fbl;

            wmma::load_matrix_sync(fbh,
                splanes + ((size_t)((2 + gate0 * 2) * FBM + wn * 16)) * FSK + ks * 16, FSK);
            wmma::load_matrix_sync(fbl,
                splanes + ((size_t)((3 + gate0 * 2) * FBM + wn * 16)) * FSK + ks * 16, FSK);
            wmma::mma_sync(acc0, fah, fbh, acc0);
            wmma::mma_sync(acc0, fah, fbl, acc0);
            wmma::mma_sync(acc0, fal, fbh, acc0);

            wmma::load_matrix_sync(fbh,
                splanes + ((size_t)((4 + gate0 * 2) * FBM + wn * 16)) * FSK + ks * 16, FSK);
            wmma::load_matrix_sync(fbl,
                splanes + ((size_t)((5 + gate0 * 2) * FBM + wn * 16)) * FSK + ks * 16, FSK);
            wmma::mma_sync(acc1, fah, fbh, acc1);
            wmma::mma_sync(acc1, fah, fbl, acc1);
            wmma::mma_sync(acc1, fal, fbh, acc1);
        }
    }

    // stage pre-activations: stage[gate][m][n]
    wmma::store_matrix_sync(&stage[gp * 2 + 0][wm * 16][wn * 16], acc0, FBN,
                            wmma::mem_row_major);
    wmma::store_matrix_sync(&stage[gp * 2 + 1][wm * 16][wn * 16], acc1, FBN,
                            wmma::mem_row_major);
    __syncthreads();

    // cell update: 1024 cells, 4 consecutive n per thread
    {
        const int row  = tid >> 3;         // 0..31
        const int col4 = (tid & 7) * 4;    // 0..28
        const int m = mbase + row;         // batch index
        const int n = nbase + col4;
        const size_t BH = (size_t)BATCH * NH;

        float4 pf = *(float4*)&stage[0][row][col4];
        float4 pi = *(float4*)&stage[1][row][col4];
        float4 pg = *(float4*)&stage[2][row][col4];
        float4 po = *(float4*)&stage[3][row][col4];
        float4 xf = *(const float4*)&g_xproj[((size_t)(0 * SEQ) + t) * BH + (size_t)m * NH + n];
        float4 xi = *(const float4*)&g_xproj[((size_t)(1 * SEQ) + t) * BH + (size_t)m * NH + n];
        float4 xg = *(const float4*)&g_xproj[((size_t)(2 * SEQ) + t) * BH + (size_t)m * NH + n];
        float4 xo = *(const float4*)&g_xproj[((size_t)(3 * SEQ) + t) * BH + (size_t)m * NH + n];
        float4 cv = *(const float4*)&g_c[(size_t)m * NH + n];

        float pfv[4]; float piv[4]; float pgv[4]; float pov[4];
        float xfv[4]; float xiv[4]; float xgv[4]; float xov[4];
        float ccv[4]; float hv[4]; float cn[4];
        pfv[0]=pf.x; pfv[1]=pf.y; pfv[2]=pf.z; pfv[3]=pf.w;
        piv[0]=pi.x; piv[1]=pi.y; piv[2]=pi.z; piv[3]=pi.w;
        pgv[0]=pg.x; pgv[1]=pg.y; pgv[2]=pg.z; pgv[3]=pg.w;
        pov[0]=po.x; pov[1]=po.y; pov[2]=po.z; pov[3]=po.w;
        xfv[0]=xf.x; xfv[1]=xf.y; xfv[2]=xf.z; xfv[3]=xf.w;
        xiv[0]=xi.x; xiv[1]=xi.y; xiv[2]=xi.z; xiv[3]=xi.w;
        xgv[0]=xg.x; xgv[1]=xg.y; xgv[2]=xg.z; xgv[3]=xg.w;
        xov[0]=xo.x; xov[1]=xo.y; xov[2]=xo.z; xov[3]=xo.w;
        ccv[0]=cv.x; ccv[1]=cv.y; ccv[2]=cv.z; ccv[3]=cv.w;

        #pragma unroll
        for (int j = 0; j < 4; j++) {
            float fg = fast_sigmoid(pfv[j] + xfv[j]);
            float ig = fast_sigmoid(piv[j] + xiv[j]);
            float gg = fast_tanh(pgv[j] + xgv[j]);
            float og = fast_sigmoid(pov[j] + xov[j]);
            float c2 = fg * ccv[j] + ig * gg;
            cn[j] = c2;
            hv[j] = og * fast_tanh(c2);
        }

        *(float4*)&g_c[(size_t)m * NH + n] = make_float4(cn[0], cn[1], cn[2], cn[3]);
        *(float4*)&g_h[(size_t)m * NH + n] = make_float4(hv[0], hv[1], hv[2], hv[3]);

        __nv_bfloat162* Hh = (__nv_bfloat162*)(hout_hi + (size_t)m * NH + n);
        __nv_bfloat162* Hl = (__nv_bfloat162*)(hout_lo + (size_t)m * NH + n);
        #pragma unroll
        for (int j = 0; j < 2; j++) {
            __nv_bfloat162 hh = __floats2bfloat162_rn(hv[2 * j], hv[2 * j + 1]);
            float l0 = hv[2 * j]     - __bfloat162float(__low2bfloat16(hh));
            float l1 = hv[2 * j + 1] - __bfloat162float(__high2bfloat16(hh));
            Hh[j] = hh;
            Hl[j] = __floats2bfloat162_rn(l0, l1);
        }
    }
}

// ---------------- bf16x3 input-projection GEMM (WMMA, as R4) ----------------
__global__ __launch_bounds__(256) void proj_gemm(Ptr4 Bias)
{
    __shared__ __align__(16) unsigned char smem_raw[49152];
    bf16* sA = (bf16*)smem_raw;
    bf16* sB = (bf16*)(smem_raw + 24576);

    const int gate = blockIdx.z;
    const bf16* __restrict__ Bhi = g_Wx_hi + (size_t)gate * NH * NIN;
    const bf16* __restrict__ Blo = g_Wx_lo + (size_t)gate * NH * NIN;
    const float* __restrict__ bias = Bias.p[gate];

    const int tid   = threadIdx.x;
    const int warp  = tid >> 5;
    const int wm    = warp >> 2;
    const int wn    = warp & 3;
    const int mbase = blockIdx.y * BM;
    const int nbase = blockIdx.x * BN;

    const int lr = tid >> 2;
    const int lc = (tid & 3) * 8;

    const bf16* pa_hi = g_x_hi + (size_t)(mbase + lr) * NIN + lc;
    const bf16* pa_lo = g_x_lo + (size_t)(mbase + lr) * NIN + lc;
    const bf16* pb_hi = Bhi + (size_t)(nbase + lr) * NIN + lc;
    const bf16* pb_lo = Blo + (size_t)(nbase + lr) * NIN + lc;

    wmma::fragment<wmma::accumulator, 16, 16, 16, float> acc0;
    wmma::fragment<wmma::accumulator, 16, 16, 16, float> acc1;
    wmma::fill_fragment(acc0, 0.0f);
    wmma::fill_fragment(acc1, 0.0f);

    const int NC = NIN / BK;   // 16

    uint4 ra_h = *(const uint4*)pa_hi;
    uint4 ra_l = *(const uint4*)pa_lo;
    uint4 rb_h = *(const uint4*)pb_hi;
    uint4 rb_l = *(const uint4*)pb_lo;
    *(uint4*)smem_tile(sA, 0, 0, lr, lc) = ra_h;
    *(uint4*)smem_tile(sA, 0, 1, lr, lc) = ra_l;
    *(uint4*)smem_tile(sB, 0, 0, lr, lc) = rb_h;
    *(uint4*)smem_tile(sB, 0, 1, lr, lc) = rb_l;
    __syncthreads();

    for (int c = 0; c < NC; c++) {
        const int st = c & 1;
        if (c + 1 < NC) {
            const int ko = (c + 1) * BK;
            ra_h = *(const uint4*)(pa_hi + ko);
            ra_l = *(const uint4*)(pa_lo + ko);
            rb_h = *(const uint4*)(pb_hi + ko);
            rb_l = *(const uint4*)(pb_lo + ko);
        }
        #pragma unroll
        for (int ks = 0; ks < 2; ks++) {
            wmma::fragment<wmma::matrix_b, 16, 16, 16, bf16, wmma::col_major> fbh;
            wmma::fragment<wmma::matrix_b, 16, 16, 16, bf16, wmma::col_major> fbl;
            wmma::load_matrix_sync(fbh, smem_tile(sB, st, 0, wn * 16, ks * 16), SKS);
            wmma::load_matrix_sync(fbl, smem_tile(sB, st, 1, wn * 16, ks * 16), SKS);

            wmma::fragment<wmma::matrix_a, 16, 16, 16, bf16, wmma::row_major> fah;
            wmma::fragment<wmma::matrix_a, 16, 16, 16, bf16, wmma::row_major> fal;
            wmma::load_matrix_sync(fah, smem_tile(sA, st, 0, wm * 32, ks * 16), SKS);
            wmma::load_matrix_sync(fal, smem_tile(sA, st, 1, wm * 32, ks * 16), SKS);
            wmma::mma_sync(acc0, fah, fbh, acc0);
            wmma::mma_sync(acc0, fah, fbl, acc0);
            wmma::mma_sync(acc0, fal, fbh, acc0);

            wmma::load_matrix_sync(fah, smem_tile(sA, st, 0, wm * 32 + 16, ks * 16), SKS);
            wmma::load_matrix_sync(fal, smem_tile(sA, st, 1, wm * 32 + 16, ks * 16), SKS);
            wmma::mma_sync(acc1, fah, fbh, acc1);
            wmma::mma_sync(acc1, fah, fbl, acc1);
            wmma::mma_sync(acc1, fal, fbh, acc1);
        }
        if (c + 1 < NC) {
            const int st2 = st ^ 1;
            *(uint4*)smem_tile(sA, st2, 0, lr, lc) = ra_h;
            *(uint4*)smem_tile(sA, st2, 1, lr, lc) = ra_l;
            *(uint4*)smem_tile(sB, st2, 0, lr, lc) = rb_h;
            *(uint4*)smem_tile(sB, st2, 1, lr, lc) = rb_l;
            __syncthreads();
        }
    }

    __syncthreads();
    float* stage = (float*)smem_raw;   // 64 x 64 floats = 16 KB
    wmma::store_matrix_sync(stage + (wm * 32) * 64 + wn * 16, acc0, 64, wmma::mem_row_major);
    wmma::store_matrix_sync(stage + (wm * 32 + 16) * 64 + wn * 16, acc1, 64, wmma::mem_row_major);
    __syncthreads();

    #pragma unroll
    for (int i = 0; i < 4; i++) {
        int e   = tid + i * 256;
        int row = e >> 4;
        int c4  = (e & 15) * 4;
        int m   = mbase + row;
        int bb  = m >> 8;
        int ss  = m & 255;
        int col = nbase + c4;
        float4 v = *(float4*)(stage + row * 64 + c4);
        v.x += bias[col + 0];
        v.y += bias[col + 1];
        v.z += bias[col + 2];
        v.w += bias[col + 3];
        *(float4*)&g_xproj[(((size_t)gate * SEQ + ss) * BATCH + bb) * NH + col] = v;
    }
}

// ---------------- fp32 output GEMM (small) ----------------
__global__ __launch_bounds__(256) void out_gemm(const float* __restrict__ Wy,
                                                const float* __restrict__ by,
                                                float* __restrict__ out)
{
    __shared__ float As[TK][SROW];
    __shared__ float Bs[TK][SROW];
    const int tid = threadIdx.x;
    const int tx = tid & 15;
    const int ty = tid >> 4;
    const int mbase = blockIdx.y * TM;
    const int nbase = blockIdx.x * TN;
    const int lm = tid >> 2;
    const int lk = (tid & 3) << 2;

    float acc[4][4];
    #pragma unroll
    for (int i = 0; i < 4; i++) {
        #pragma unroll
        for (int j = 0; j < 4; j++) { acc[i][j] = 0.f; }
    }

    for (int kt = 0; kt < NH; kt += TK) {
        float4 av = *(const float4*)&g_h[(size_t)(mbase + lm) * NH + kt + lk];
        float4 bv = *(const float4*)&Wy [(size_t)(nbase + lm) * NH + kt + lk];
        __syncthreads();
        As[lk + 0][lm] = av.x; As[lk + 1][lm] = av.y;
        As[lk + 2][lm] = av.z; As[lk + 3][lm] = av.w;
        Bs[lk + 0][lm] = bv.x; Bs[lk + 1][lm] = bv.y;
        Bs[lk + 2][lm] = bv.z; Bs[lk + 3][lm] = bv.w;
        __syncthreads();
        #pragma unroll
        for (int k = 0; k < TK; k++) {
            float ar[4]; float br[4];
            #pragma unroll
            for (int i = 0; i < 4; i++) { ar[i] = As[k][(ty << 2) + i]; }
            #pragma unroll
            for (int j = 0; j < 4; j++) { br[j] = Bs[k][(tx << 2) + j]; }
            #pragma unroll
            for (int i = 0; i < 4; i++) {
                #pragma unroll
                for (int j = 0; j < 4; j++) { acc[i][j] = fmaf(ar[i], br[j], acc[i][j]); }
            }
        }
    }

    #pragma unroll
    for (int i = 0; i < 4; i++) {
        int m = mbase + (ty << 2) + i;
        int n0 = nbase + (tx << 2);
        #pragma unroll
        for (int j = 0; j < 4; j++) {
            out[(size_t)m * NOUT + n0 + j] = acc[i][j] + by[n0 + j];
        }
    }
}

__global__ __launch_bounds__(256) void copy_hc(float* __restrict__ out)
{
    const int idx = blockIdx.x * 256 + threadIdx.x;  // grid 512
    out[(size_t)BATCH * NOUT + idx]                      = g_h[idx];
    out[(size_t)BATCH * NOUT + (size_t)BATCH * NH + idx] = g_c[idx];
}

// ---------------------------------------------------------------------------
extern "C" void kernel_launch(void* const* d_in, const int* in_sizes, int n_in,
                              void* d_out, int out_size)
{
    const float* x_seq = (const float*)d_in[0];
    Ptr4 Wx; Ptr4 Bx; Ptr4 Wh;
    Wx.p[0] = (const float*)d_in[1];  Bx.p[0] = (const float*)d_in[2];  Wh.p[0] = (const float*)d_in[3];
    Wx.p[1] = (const float*)d_in[4];  Bx.p[1] = (const float*)d_in[5];  Wh.p[1] = (const float*)d_in[6];
    Wx.p[2] = (const float*)d_in[7];  Bx.p[2] = (const float*)d_in[8];  Wh.p[2] = (const float*)d_in[9];
    Wx.p[3] = (const float*)d_in[10]; Bx.p[3] = (const float*)d_in[11]; Wh.p[3] = (const float*)d_in[12];
    const float* Why_w = (const float*)d_in[13];
    const float* Why_b = (const float*)d_in[14];
    float* out = (float*)d_out;

    init_state<<<512, 256>>>();

    split_wh<<<(4 * NH * NH) / 256, 256>>>(Wh);
    split_wx<<<(4 * NH * NIN) / 256, 256>>>(Wx);
    split_x<<<(BATCH * SEQ * NIN) / 256, 256>>>(x_seq);

    proj_gemm<<<dim3(NH / BN, (BATCH * SEQ) / BM, 4), 256>>>(Bx);

    for (int t = 0; t < SEQ; t++) {
        rec_step<<<dim3(NH / FBN, BATCH / FBM), 256>>>(t);
    }

    out_gemm<<<dim3(NOUT / TN, BATCH / TM), 256>>>(Why_w, Why_b, out);
    copy_hc<<<512, 256>>>(out);
}

// round 7
// speedup vs baseline: 1.9937x; 1.2156x over previous
#include <cuda_runtime.h>
#include <cuda_bf16.h>
#include <mma.h>
#include <cuda_pipeline.h>

using namespace nvcuda;

#define BATCH 128
#define SEQ   256
#define NIN   512
#define NH    1024
#define NOUT  512

typedef __nv_bfloat16 bf16;

// proj GEMM tiling
#define BM 64
#define BN 64
#define BK 32
#define SKS 48
#define PSTAGES 3
#define PSTB (4 * BM * SKS)            /* bf16 per proj stage  */

// fused rec-step tiling
#define FBM 32
#define FBN 32
#define FBK 32
#define FSK 40
#define RSTAGES 3
#define RSTB (10 * FBM * FSK)          /* bf16 per rec stage */

// fp32 out_gemm tiling
#define TM 64
#define TN 64
#define TK 16
#define SROW 68

// ---------------- scratch (device globals) ----------------
__device__ float g_xproj[(size_t)4 * SEQ * BATCH * NH];
__device__ float g_h[BATCH * NH];
__device__ float g_c[BATCH * NH];
__device__ bf16  g_hA_hi[BATCH * NH];
__device__ bf16  g_hA_lo[BATCH * NH];
__device__ bf16  g_hB_hi[BATCH * NH];
__device__ bf16  g_hB_lo[BATCH * NH];
__device__ bf16  g_Wh_hi[(size_t)4 * NH * NH];
__device__ bf16  g_Wh_lo[(size_t)4 * NH * NH];
__device__ bf16  g_Wx_hi[(size_t)4 * NH * NIN];
__device__ bf16  g_Wx_lo[(size_t)4 * NH * NIN];
__device__ bf16  g_x_hi[(size_t)BATCH * SEQ * NIN];
__device__ bf16  g_x_lo[(size_t)BATCH * SEQ * NIN];

struct Ptr4 { const float* p[4]; };

__device__ __forceinline__ float fast_sigmoid(float x) { return 1.f / (1.f + __expf(-x)); }
__device__ __forceinline__ float fast_tanh(float x)    { return 2.f * fast_sigmoid(2.f * x) - 1.f; }

// ---------------- init / split kernels ----------------
__global__ __launch_bounds__(256) void init_state()
{
    int idx = blockIdx.x * 256 + threadIdx.x;  // grid 512
    g_h[idx] = 0.f;
    g_c[idx] = 0.f;
    g_hA_hi[idx] = __float2bfloat16_rn(0.f);
    g_hA_lo[idx] = __float2bfloat16_rn(0.f);
}

__global__ __launch_bounds__(256) void split_wh(Ptr4 W)
{
    size_t idx = (size_t)blockIdx.x * 256 + threadIdx.x;  // 4 * 2^20
    int gate = (int)(idx >> 20);
    float v = W.p[gate][idx & ((1u << 20) - 1)];
    bf16 hv = __float2bfloat16_rn(v);
    g_Wh_hi[idx] = hv;
    g_Wh_lo[idx] = __float2bfloat16_rn(v - __bfloat162float(hv));
}

__global__ __launch_bounds__(256) void split_wx(Ptr4 W)
{
    size_t idx = (size_t)blockIdx.x * 256 + threadIdx.x;  // 4 * 2^19
    int gate = (int)(idx >> 19);
    float v = W.p[gate][idx & ((1u << 19) - 1)];
    bf16 hv = __float2bfloat16_rn(v);
    g_Wx_hi[idx] = hv;
    g_Wx_lo[idx] = __float2bfloat16_rn(v - __bfloat162float(hv));
}

__global__ __launch_bounds__(256) void split_x(const float* __restrict__ x)
{
    size_t idx = (size_t)blockIdx.x * 256 + threadIdx.x;  // 2^24
    float v = x[idx];
    bf16 hv = __float2bfloat16_rn(v);
    g_x_hi[idx] = hv;
    g_x_lo[idx] = __float2bfloat16_rn(v - __bfloat162float(hv));
}

// ---------------- fused recurrent step (cp.async 3-stage) ----------------
// grid (NH/FBN=32, BATCH/FBM=4) = 128 blocks, 256 threads.
__global__ __launch_bounds__(256) void rec_step(int t)
{
    extern __shared__ __align__(16) unsigned char dynsm[];
    bf16*  stg   = (bf16*)dynsm;                                 // RSTAGES stages
    float* stage = (float*)(dynsm + (size_t)RSTAGES * RSTB * 2); // [4][32][32]

    const int par = t & 1;
    const bf16* __restrict__ hin_hi = par ? g_hB_hi : g_hA_hi;
    const bf16* __restrict__ hin_lo = par ? g_hB_lo : g_hA_lo;
    bf16* __restrict__ hout_hi = par ? g_hA_hi : g_hB_hi;
    bf16* __restrict__ hout_lo = par ? g_hA_lo : g_hB_lo;

    const int tid   = threadIdx.x;
    const int nbase = blockIdx.x * FBN;
    const int mbase = blockIdx.y * FBM;

    // loader: 1280 16B-chunks per stage (10 planes x 32 rows x 4 chunks), 5/thread
    const bf16* gsrc[5];
    int soff[5];
    #pragma unroll
    for (int l = 0; l < 5; l++) {
        int idx = l * 256 + tid;
        int p   = idx >> 7;          // plane 0..9
        int w   = idx & 127;
        int row = w >> 2;
        int q   = (w & 3) * 8;       // 0..24 bf16, covers k 0..31
        soff[l] = (p * FBM + row) * FSK + q;
        if (p == 0) {
            gsrc[l] = hin_hi + (size_t)(mbase + row) * NH + q;
        } else if (p == 1) {
            gsrc[l] = hin_lo + (size_t)(mbase + row) * NH + q;
        } else {
            int g2   = p - 2;
            int gate = g2 >> 1;
            int islo = g2 & 1;
            const bf16* wbase = islo ? g_Wh_lo : g_Wh_hi;
            gsrc[l] = wbase + (size_t)gate * NH * NH + (size_t)(nbase + row) * NH + q;
        }
    }

    const int warp = tid >> 5;
    const int wm = (warp >> 2) & 1;
    const int wn = (warp >> 1) & 1;
    const int gp = warp & 1;

    wmma::fragment<wmma::accumulator, 16, 16, 16, float> acc0;
    wmma::fragment<wmma::accumulator, 16, 16, 16, float> acc1;
    wmma::fill_fragment(acc0, 0.0f);
    wmma::fill_fragment(acc1, 0.0f);

    const int NC = NH / FBK;   // 32

    #pragma unroll
    for (int s = 0; s < RSTAGES - 1; s++) {
        const int ko = s * FBK;
        #pragma unroll
        for (int l = 0; l < 5; l++) {
            __pipeline_memcpy_async(stg + s * RSTB + soff[l], gsrc[l] + ko, 16);
        }
        __pipeline_commit();
    }

    for (int c = 0; c < NC; c++) {
        __pipeline_wait_prior(RSTAGES - 2);
        __syncthreads();

        const int cn = c + RSTAGES - 1;
        if (cn < NC) {
            const int ko = cn * FBK;
            const int ds = cn % RSTAGES;
            #pragma unroll
            for (int l = 0; l < 5; l++) {
                __pipeline_memcpy_async(stg + ds * RSTB + soff[l], gsrc[l] + ko, 16);
            }
        }
        __pipeline_commit();

        bf16* sp = stg + (c % RSTAGES) * RSTB;
        #pragma unroll
        for (int ks = 0; ks < 2; ks++) {
            wmma::fragment<wmma::matrix_a, 16, 16, 16, bf16, wmma::row_major> fah;
            wmma::fragment<wmma::matrix_a, 16, 16, 16, bf16, wmma::row_major> fal;
            wmma::load_matrix_sync(fah, sp + (0 * FBM + wm * 16) * FSK + ks * 16, FSK);
            wmma::load_matrix_sync(fal, sp + (1 * FBM + wm * 16) * FSK + ks * 16, FSK);

            const int gate0 = gp * 2;
            wmma::fragment<wmma::matrix_b, 16, 16, 16, bf16, wmma::col_major> fbh;
            wmma::fragment<wmma::matrix_b, 16, 16, 16, bf16, wmma::col_major> fbl;

            wmma::load_matrix_sync(fbh, sp + ((2 + gate0 * 2) * FBM + wn * 16) * FSK + ks * 16, FSK);
            wmma::load_matrix_sync(fbl, sp + ((3 + gate0 * 2) * FBM + wn * 16) * FSK + ks * 16, FSK);
            wmma::mma_sync(acc0, fah, fbh, acc0);
            wmma::mma_sync(acc0, fah, fbl, acc0);
            wmma::mma_sync(acc0, fal, fbh, acc0);

            wmma::load_matrix_sync(fbh, sp + ((4 + gate0 * 2) * FBM + wn * 16) * FSK + ks * 16, FSK);
            wmma::load_matrix_sync(fbl, sp + ((5 + gate0 * 2) * FBM + wn * 16) * FSK + ks * 16, FSK);
            wmma::mma_sync(acc1, fah, fbh, acc1);
            wmma::mma_sync(acc1, fah, fbl, acc1);
            wmma::mma_sync(acc1, fal, fbh, acc1);
        }
    }

    float* st0 = stage + ((gp * 2 + 0) * FBM + wm * 16) * FBN + wn * 16;
    float* st1 = stage + ((gp * 2 + 1) * FBM + wm * 16) * FBN + wn * 16;
    wmma::store_matrix_sync(st0, acc0, FBN, wmma::mem_row_major);
    wmma::store_matrix_sync(st1, acc1, FBN, wmma::mem_row_major);
    __syncthreads();

    // cell update: 1024 cells, 4 consecutive n per thread
    {
        const int row  = tid >> 3;
        const int col4 = (tid & 7) * 4;
        const int m = mbase + row;
        const int n = nbase + col4;
        const size_t BH = (size_t)BATCH * NH;

        float4 pf = *(float4*)(stage + (0 * FBM + row) * FBN + col4);
        float4 pi = *(float4*)(stage + (1 * FBM + row) * FBN + col4);
        float4 pg = *(float4*)(stage + (2 * FBM + row) * FBN + col4);
        float4 po = *(float4*)(stage + (3 * FBM + row) * FBN + col4);
        float4 xf = *(const float4*)&g_xproj[((size_t)(0 * SEQ) + t) * BH + (size_t)m * NH + n];
        float4 xi = *(const float4*)&g_xproj[((size_t)(1 * SEQ) + t) * BH + (size_t)m * NH + n];
        float4 xg = *(const float4*)&g_xproj[((size_t)(2 * SEQ) + t) * BH + (size_t)m * NH + n];
        float4 xo = *(const float4*)&g_xproj[((size_t)(3 * SEQ) + t) * BH + (size_t)m * NH + n];
        float4 cv = *(const float4*)&g_c[(size_t)m * NH + n];

        float pfv[4]; float piv[4]; float pgv[4]; float pov[4];
        float xfv[4]; float xiv[4]; float xgv[4]; float xov[4];
        float ccv[4]; float hv[4]; float cn2[4];
        pfv[0]=pf.x; pfv[1]=pf.y; pfv[2]=pf.z; pfv[3]=pf.w;
        piv[0]=pi.x; piv[1]=pi.y; piv[2]=pi.z; piv[3]=pi.w;
        pgv[0]=pg.x; pgv[1]=pg.y; pgv[2]=pg.z; pgv[3]=pg.w;
        pov[0]=po.x; pov[1]=po.y; pov[2]=po.z; pov[3]=po.w;
        xfv[0]=xf.x; xfv[1]=xf.y; xfv[2]=xf.z; xfv[3]=xf.w;
        xiv[0]=xi.x; xiv[1]=xi.y; xiv[2]=xi.z; xiv[3]=xi.w;
        xgv[0]=xg.x; xgv[1]=xg.y; xgv[2]=xg.z; xgv[3]=xg.w;
        xov[0]=xo.x; xov[1]=xo.y; xov[2]=xo.z; xov[3]=xo.w;
        ccv[0]=cv.x; ccv[1]=cv.y; ccv[2]=cv.z; ccv[3]=cv.w;

        #pragma unroll
        for (int j = 0; j < 4; j++) {
            float fg = fast_sigmoid(pfv[j] + xfv[j]);
            float ig = fast_sigmoid(piv[j] + xiv[j]);
            float gg = fast_tanh(pgv[j] + xgv[j]);
            float og = fast_sigmoid(pov[j] + xov[j]);
            float c2 = fg * ccv[j] + ig * gg;
            cn2[j] = c2;
            hv[j] = og * fast_tanh(c2);
        }

        *(float4*)&g_c[(size_t)m * NH + n] = make_float4(cn2[0], cn2[1], cn2[2], cn2[3]);
        *(float4*)&g_h[(size_t)m * NH + n] = make_float4(hv[0], hv[1], hv[2], hv[3]);

        __nv_bfloat162* Hh = (__nv_bfloat162*)(hout_hi + (size_t)m * NH + n);
        __nv_bfloat162* Hl = (__nv_bfloat162*)(hout_lo + (size_t)m * NH + n);
        #pragma unroll
        for (int j = 0; j < 2; j++) {
            __nv_bfloat162 hh = __floats2bfloat162_rn(hv[2 * j], hv[2 * j + 1]);
            float l0 = hv[2 * j]     - __bfloat162float(__low2bfloat16(hh));
            float l1 = hv[2 * j + 1] - __bfloat162float(__high2bfloat16(hh));
            Hh[j] = hh;
            Hl[j] = __floats2bfloat162_rn(l0, l1);
        }
    }
}

// ---------------- bf16x3 input-projection GEMM (cp.async 3-stage) ----------------
// grid (NH/BN=16, BATCH*SEQ/BM=512, 4); block 256.
// stage planes: 0 = A hi, 1 = A lo, 2 = B hi, 3 = B lo (64 rows x SKS each)
__global__ __launch_bounds__(256) void proj_gemm(Ptr4 Bias)
{
    extern __shared__ __align__(16) unsigned char dynsm[];
    bf16* stg = (bf16*)dynsm;   // PSTAGES stages of PSTB bf16

    const int gate = blockIdx.z;
    const bf16* __restrict__ Bhi = g_Wx_hi + (size_t)gate * NH * NIN;
    const bf16* __restrict__ Blo = g_Wx_lo + (size_t)gate * NH * NIN;
    const float* __restrict__ bias = Bias.p[gate];

    const int tid   = threadIdx.x;
    const int warp  = tid >> 5;
    const int wm    = warp >> 2;
    const int wn    = warp & 3;
    const int mbase = blockIdx.y * BM;
    const int nbase = blockIdx.x * BN;

    // loader: 1024 16B-chunks per stage (4 planes x 64 rows x 4 chunks), 4/thread
    const bf16* gsrc[4];
    int soff[4];
    #pragma unroll
    for (int l = 0; l < 4; l++) {
        int idx = l * 256 + tid;
        int p   = idx >> 8;          // plane 0..3
        int w   = idx & 255;
        int row = w >> 2;            // 0..63
        int q   = (w & 3) * 8;       // 0..24 bf16, covers k 0..31
        soff[l] = (p * BM + row) * SKS + q;
        if (p == 0) {
            gsrc[l] = g_x_hi + (size_t)(mbase + row) * NIN + q;
        } else if (p == 1) {
            gsrc[l] = g_x_lo + (size_t)(mbase + row) * NIN + q;
        } else if (p == 2) {
            gsrc[l] = Bhi + (size_t)(nbase + row) * NIN + q;
        } else {
            gsrc[l] = Blo + (size_t)(nbase + row) * NIN + q;
        }
    }

    wmma::fragment<wmma::accumulator, 16, 16, 16, float> acc0;
    wmma::fragment<wmma::accumulator, 16, 16, 16, float> acc1;
    wmma::fill_fragment(acc0, 0.0f);
    wmma::fill_fragment(acc1, 0.0f);

    const int NC = NIN / BK;   // 16

    #pragma unroll
    for (int s = 0; s < PSTAGES - 1; s++) {
        const int ko = s * BK;
        #pragma unroll
        for (int l = 0; l < 4; l++) {
            __pipeline_memcpy_async(stg + s * PSTB + soff[l], gsrc[l] + ko, 16);
        }
        __pipeline_commit();
    }

    for (int c = 0; c < NC; c++) {
        __pipeline_wait_prior(PSTAGES - 2);
        __syncthreads();

        const int cn = c + PSTAGES - 1;
        if (cn < NC) {
            const int ko = cn * BK;
            const int ds = cn % PSTAGES;
            #pragma unroll
            for (int l = 0; l < 4; l++) {
                __pipeline_memcpy_async(stg + ds * PSTB + soff[l], gsrc[l] + ko, 16);
            }
        }
        __pipeline_commit();

        bf16* sp = stg + (c % PSTAGES) * PSTB;
        #pragma unroll
        for (int ks = 0; ks < 2; ks++) {
            wmma::fragment<wmma::matrix_b, 16, 16, 16, bf16, wmma::col_major> fbh;
            wmma::fragment<wmma::matrix_b, 16, 16, 16, bf16, wmma::col_major> fbl;
            wmma::load_matrix_sync(fbh, sp + (2 * BM + wn * 16) * SKS + ks * 16, SKS);
            wmma::load_matrix_sync(fbl, sp + (3 * BM + wn * 16) * SKS + ks * 16, SKS);

            wmma::fragment<wmma::matrix_a, 16, 16, 16, bf16, wmma::row_major> fah;
            wmma::fragment<wmma::matrix_a, 16, 16, 16, bf16, wmma::row_major> fal;
            wmma::load_matrix_sync(fah, sp + (0 * BM + wm * 32) * SKS + ks * 16, SKS);
            wmma::load_matrix_sync(fal, sp + (1 * BM + wm * 32) * SKS + ks * 16, SKS);
            wmma::mma_sync(acc0, fah, fbh, acc0);
            wmma::mma_sync(acc0, fah, fbl, acc0);
            wmma::mma_sync(acc0, fal, fbh, acc0);

            wmma::load_matrix_sync(fah, sp + (0 * BM + wm * 32 + 16) * SKS + ks * 16, SKS);
            wmma::load_matrix_sync(fal, sp + (1 * BM + wm * 32 + 16) * SKS + ks * 16, SKS);
            wmma::mma_sync(acc1, fah, fbh, acc1);
            wmma::mma_sync(acc1, fah, fbl, acc1);
            wmma::mma_sync(acc1, fal, fbh, acc1);
        }
    }

    // epilogue: drain pipeline, then overlay fp32 stage on the buffers
    __pipeline_wait_prior(0);
    __syncthreads();
    float* stage = (float*)dynsm;   // 64 x 64 floats = 16 KB
    wmma::store_matrix_sync(stage + (wm * 32) * 64 + wn * 16, acc0, 64, wmma::mem_row_major);
    wmma::store_matrix_sync(stage + (wm * 32 + 16) * 64 + wn * 16, acc1, 64, wmma::mem_row_major);
    __syncthreads();

    #pragma unroll
    for (int i = 0; i < 4; i++) {
        int e   = tid + i * 256;
        int row = e >> 4;
        int c4  = (e & 15) * 4;
        int m   = mbase + row;
        int bb  = m >> 8;
        int ss  = m & 255;
        int col = nbase + c4;
        float4 v = *(float4*)(stage + row * 64 + c4);
        v.x += bias[col + 0];
        v.y += bias[col + 1];
        v.z += bias[col + 2];
        v.w += bias[col + 3];
        *(float4*)&g_xproj[(((size_t)gate * SEQ + ss) * BATCH + bb) * NH + col] = v;
    }
}

// ---------------- fp32 output GEMM (small) ----------------
__global__ __launch_bounds__(256) void out_gemm(const float* __restrict__ Wy,
                                                const float* __restrict__ by,
                                                float* __restrict__ out)
{
    __shared__ float As[TK][SROW];
    __shared__ float Bs[TK][SROW];
    const int tid = threadIdx.x;
    const int tx = tid & 15;
    const int ty = tid >> 4;
    const int mbase = blockIdx.y * TM;
    const int nbase = blockIdx.x * TN;
    const int lm = tid >> 2;
    const int lk = (tid & 3) << 2;

    float acc[4][4];
    #pragma unroll
    for (int i = 0; i < 4; i++) {
        #pragma unroll
        for (int j = 0; j < 4; j++) { acc[i][j] = 0.f; }
    }

    for (int kt = 0; kt < NH; kt += TK) {
        float4 av = *(const float4*)&g_h[(size_t)(mbase + lm) * NH + kt + lk];
        float4 bv = *(const float4*)&Wy [(size_t)(nbase + lm) * NH + kt + lk];
        __syncthreads();
        As[lk + 0][lm] = av.x; As[lk + 1][lm] = av.y;
        As[lk + 2][lm] = av.z; As[lk + 3][lm] = av.w;
        Bs[lk + 0][lm] = bv.x; Bs[lk + 1][lm] = bv.y;
        Bs[lk + 2][lm] = bv.z; Bs[lk + 3][lm] = bv.w;
        __syncthreads();
        #pragma unroll
        for (int k = 0; k < TK; k++) {
            float ar[4]; float br[4];
            #pragma unroll
            for (int i = 0; i < 4; i++) { ar[i] = As[k][(ty << 2) + i]; }
            #pragma unroll
            for (int j = 0; j < 4; j++) { br[j] = Bs[k][(tx << 2) + j]; }
            #pragma unroll
            for (int i = 0; i < 4; i++) {
                #pragma unroll
                for (int j = 0; j < 4; j++) { acc[i][j] = fmaf(ar[i], br[j], acc[i][j]); }
            }
        }
    }

    #pragma unroll
    for (int i = 0; i < 4; i++) {
        int m = mbase + (ty << 2) + i;
        int n0 = nbase + (tx << 2);
        #pragma unroll
        for (int j = 0; j < 4; j++) {
            out[(size_t)m * NOUT + n0 + j] = acc[i][j] + by[n0 + j];
        }
    }
}

__global__ __launch_bounds__(256) void copy_hc(float* __restrict__ out)
{
    const int idx = blockIdx.x * 256 + threadIdx.x;  // grid 512
    out[(size_t)BATCH * NOUT + idx]                      = g_h[idx];
    out[(size_t)BATCH * NOUT + (size_t)BATCH * NH + idx] = g_c[idx];
}

// ---------------------------------------------------------------------------
extern "C" void kernel_launch(void* const* d_in, const int* in_sizes, int n_in,
                              void* d_out, int out_size)
{
    const float* x_seq = (const float*)d_in[0];
    Ptr4 Wx; Ptr4 Bx; Ptr4 Wh;
    Wx.p[0] = (const float*)d_in[1];  Bx.p[0] = (const float*)d_in[2];  Wh.p[0] = (const float*)d_in[3];
    Wx.p[1] = (const float*)d_in[4];  Bx.p[1] = (const float*)d_in[5];  Wh.p[1] = (const float*)d_in[6];
    Wx.p[2] = (const float*)d_in[7];  Bx.p[2] = (const float*)d_in[8];  Wh.p[2] = (const float*)d_in[9];
    Wx.p[3] = (const float*)d_in[10]; Bx.p[3] = (const float*)d_in[11]; Wh.p[3] = (const float*)d_in[12];
    const float* Why_w = (const float*)d_in[13];
    const float* Why_b = (const float*)d_in[14];
    float* out = (float*)d_out;

    const int rec_smem  = RSTAGES * RSTB * 2 + 4 * FBM * FBN * 4;   // 93184 B
    const int proj_smem = PSTAGES * PSTB * 2;                       // 73728 B
    cudaFuncSetAttribute(rec_step,  cudaFuncAttributeMaxDynamicSharedMemorySize, rec_smem);
    cudaFuncSetAttribute(proj_gemm, cudaFuncAttributeMaxDynamicSharedMemorySize, proj_smem);

    init_state<<<512, 256>>>();

    split_wh<<<(4 * NH * NH) / 256, 256>>>(Wh);
    split_wx<<<(4 * NH * NIN) / 256, 256>>>(Wx);
    split_x<<<(BATCH * SEQ * NIN) / 256, 256>>>(x_seq);

    proj_gemm<<<dim3(NH / BN, (BATCH * SEQ) / BM, 4), 256, proj_smem>>>(Bx);

    for (int t = 0; t < SEQ; t++) {
        rec_step<<<dim3(NH / FBN, BATCH / FBM), 256, rec_smem>>>(t);
    }

    out_gemm<<<dim3(NOUT / TN, BATCH / TM), 256>>>(Why_w, Why_b, out);
    copy_hc<<<512, 256>>>(out);
}

// round 8
// speedup vs baseline: 2.1025x; 1.0546x over previous
#include <cuda_runtime.h>
#include <cuda_bf16.h>
#include <mma.h>
#include <cuda_pipeline.h>

using namespace nvcuda;

#define BATCH 128
#define SEQ   256
#define NIN   512
#define NH    1024
#define NOUT  512

typedef __nv_bfloat16 bf16;

// proj GEMM tiling
#define BM 64
#define BN 64
#define BK 32
#define SKS 48
#define PSTAGES 3
#define PSTB (4 * BM * SKS)

// fused rec-step tiling: 64 m x (16 n per gate x 4 gates), K-tile 32
#define FBM 64
#define FBNG 16
#define FBK 32
#define FSK 40
#define RSTAGES 3
#define RROWS 256                      /* 2 A planes x 64 + 8 B planes x 16 */
#define RSTB (RROWS * FSK)             /* bf16 per rec stage = 10240 */

// fp32 out_gemm tiling
#define TM 64
#define TN 64
#define TK 16
#define SROW 68

// ---------------- scratch (device globals) ----------------
__device__ float g_xproj[(size_t)4 * SEQ * BATCH * NH];
__device__ float g_h[BATCH * NH];
__device__ float g_c[BATCH * NH];
__device__ bf16  g_hA_hi[BATCH * NH];
__device__ bf16  g_hA_lo[BATCH * NH];
__device__ bf16  g_hB_hi[BATCH * NH];
__device__ bf16  g_hB_lo[BATCH * NH];
__device__ bf16  g_Wh_hi[(size_t)4 * NH * NH];
__device__ bf16  g_Wh_lo[(size_t)4 * NH * NH];
__device__ bf16  g_Wx_hi[(size_t)4 * NH * NIN];
__device__ bf16  g_Wx_lo[(size_t)4 * NH * NIN];
__device__ bf16  g_x_hi[(size_t)BATCH * SEQ * NIN];
__device__ bf16  g_x_lo[(size_t)BATCH * SEQ * NIN];

struct Ptr4 { const float* p[4]; };

__device__ __forceinline__ float fast_sigmoid(float x) { return 1.f / (1.f + __expf(-x)); }
__device__ __forceinline__ float fast_tanh(float x)    { return 2.f * fast_sigmoid(2.f * x) - 1.f; }

// ---------------- init / split kernels ----------------
__global__ __launch_bounds__(256) void init_state()
{
    int idx = blockIdx.x * 256 + threadIdx.x;  // grid 512
    g_h[idx] = 0.f;
    g_c[idx] = 0.f;
    g_hA_hi[idx] = __float2bfloat16_rn(0.f);
    g_hA_lo[idx] = __float2bfloat16_rn(0.f);
}

__global__ __launch_bounds__(256) void split_wh(Ptr4 W)
{
    size_t idx = (size_t)blockIdx.x * 256 + threadIdx.x;  // 4 * 2^20
    int gate = (int)(idx >> 20);
    float v = W.p[gate][idx & ((1u << 20) - 1)];
    bf16 hv = __float2bfloat16_rn(v);
    g_Wh_hi[idx] = hv;
    g_Wh_lo[idx] = __float2bfloat16_rn(v - __bfloat162float(hv));
}

__global__ __launch_bounds__(256) void split_wx(Ptr4 W)
{
    size_t idx = (size_t)blockIdx.x * 256 + threadIdx.x;  // 4 * 2^19
    int gate = (int)(idx >> 19);
    float v = W.p[gate][idx & ((1u << 19) - 1)];
    bf16 hv = __float2bfloat16_rn(v);
    g_Wx_hi[idx] = hv;
    g_Wx_lo[idx] = __float2bfloat16_rn(v - __bfloat162float(hv));
}

__global__ __launch_bounds__(256) void split_x(const float* __restrict__ x)
{
    size_t idx = (size_t)blockIdx.x * 256 + threadIdx.x;  // 2^24
    float v = x[idx];
    bf16 hv = __float2bfloat16_rn(v);
    g_x_hi[idx] = hv;
    g_x_lo[idx] = __float2bfloat16_rn(v - __bfloat162float(hv));
}

// ---------------- fused recurrent step (64m x 16n/gate, cp.async) ----------------
// grid (NH/FBNG=64, BATCH/FBM=2) = 128 blocks, 256 threads (8 warps).
// Stage rows: [0,64)=h hi, [64,128)=h lo, [128+p2*16) p2=gate*2+isLo = W planes.
// Warp (gp=warp>>1 gate, wm=warp&1 m-half) computes 32m x 16n for its gate.
__global__ __launch_bounds__(256) void rec_step(int t)
{
    extern __shared__ __align__(16) unsigned char dynsm[];
    bf16*  stg   = (bf16*)dynsm;                                 // RSTAGES stages
    float* stage = (float*)(dynsm + (size_t)RSTAGES * RSTB * 2); // [4][64][16]

    const int par = t & 1;
    const bf16* __restrict__ hin_hi = par ? g_hB_hi : g_hA_hi;
    const bf16* __restrict__ hin_lo = par ? g_hB_lo : g_hA_lo;
    bf16* __restrict__ hout_hi = par ? g_hA_hi : g_hB_hi;
    bf16* __restrict__ hout_lo = par ? g_hA_lo : g_hB_lo;

    const int tid   = threadIdx.x;
    const int nbase = blockIdx.x * FBNG;
    const int mbase = blockIdx.y * FBM;

    // loader: 1024 16B-chunks per stage (256 rows x 4 chunks), 4 per thread
    const bf16* gsrc[4];
    int soff[4];
    #pragma unroll
    for (int l = 0; l < 4; l++) {
        int idx  = l * 256 + tid;
        int row  = idx >> 2;          // 0..255
        int q    = (idx & 3) * 8;     // 0..24 bf16 (covers k 0..31)
        soff[l]  = row * FSK + q;
        if (row < 64) {
            gsrc[l] = hin_hi + (size_t)(mbase + row) * NH + q;
        } else if (row < 128) {
            gsrc[l] = hin_lo + (size_t)(mbase + row - 64) * NH + q;
        } else {
            int b    = row - 128;
            int p2   = b >> 4;        // 0..7
            int r    = b & 15;
            int gate = p2 >> 1;
            int islo = p2 & 1;
            const bf16* wbase = islo ? g_Wh_lo : g_Wh_hi;
            gsrc[l] = wbase + (size_t)gate * NH * NH + (size_t)(nbase + r) * NH + q;
        }
    }

    const int warp = tid >> 5;
    const int gp = warp >> 1;     // gate 0..3
    const int wm = warp & 1;      // m-half 0..1

    wmma::fragment<wmma::accumulator, 16, 16, 16, float> acc0;
    wmma::fragment<wmma::accumulator, 16, 16, 16, float> acc1;
    wmma::fill_fragment(acc0, 0.0f);
    wmma::fill_fragment(acc1, 0.0f);

    const int NC = NH / FBK;   // 32

    #pragma unroll
    for (int s = 0; s < RSTAGES - 1; s++) {
        const int ko = s * FBK;
        #pragma unroll
        for (int l = 0; l < 4; l++) {
            __pipeline_memcpy_async(stg + s * RSTB + soff[l], gsrc[l] + ko, 16);
        }
        __pipeline_commit();
    }

    for (int c = 0; c < NC; c++) {
        __pipeline_wait_prior(RSTAGES - 2);
        __syncthreads();

        const int cn = c + RSTAGES - 1;
        if (cn < NC) {
            const int ko = cn * FBK;
            const int ds = cn % RSTAGES;
            #pragma unroll
            for (int l = 0; l < 4; l++) {
                __pipeline_memcpy_async(stg + ds * RSTB + soff[l], gsrc[l] + ko, 16);
            }
        }
        __pipeline_commit();

        bf16* sp = stg + (c % RSTAGES) * RSTB;
        #pragma unroll
        for (int ks = 0; ks < 2; ks++) {
            wmma::fragment<wmma::matrix_b, 16, 16, 16, bf16, wmma::col_major> fbh;
            wmma::fragment<wmma::matrix_b, 16, 16, 16, bf16, wmma::col_major> fbl;
            wmma::load_matrix_sync(fbh, sp + (128 + gp * 32) * FSK + ks * 16, FSK);
            wmma::load_matrix_sync(fbl, sp + (128 + gp * 32 + 16) * FSK + ks * 16, FSK);

            wmma::fragment<wmma::matrix_a, 16, 16, 16, bf16, wmma::row_major> fah;
            wmma::fragment<wmma::matrix_a, 16, 16, 16, bf16, wmma::row_major> fal;

            wmma::load_matrix_sync(fah, sp + (wm * 32) * FSK + ks * 16, FSK);
            wmma::load_matrix_sync(fal, sp + (64 + wm * 32) * FSK + ks * 16, FSK);
            wmma::mma_sync(acc0, fah, fbh, acc0);
            wmma::mma_sync(acc0, fah, fbl, acc0);
            wmma::mma_sync(acc0, fal, fbh, acc0);

            wmma::load_matrix_sync(fah, sp + (wm * 32 + 16) * FSK + ks * 16, FSK);
            wmma::load_matrix_sync(fal, sp + (64 + wm * 32 + 16) * FSK + ks * 16, FSK);
            wmma::mma_sync(acc1, fah, fbh, acc1);
            wmma::mma_sync(acc1, fah, fbl, acc1);
            wmma::mma_sync(acc1, fal, fbh, acc1);
        }
    }

    // stage pre-activations: stage[gate][m 0..63][n 0..15]
    wmma::store_matrix_sync(stage + ((gp * FBM) + (wm * 32 + 0)) * FBNG,  acc0, FBNG,
                            wmma::mem_row_major);
    wmma::store_matrix_sync(stage + ((gp * FBM) + (wm * 32 + 16)) * FBNG, acc1, FBNG,
                            wmma::mem_row_major);
    __syncthreads();

    // cell update: 64m x 16n = 1024 cells, 4 consecutive n per thread
    {
        const int row  = tid >> 2;         // 0..63
        const int col4 = (tid & 3) * 4;    // 0,4,8,12
        const int m = mbase + row;
        const int n = nbase + col4;
        const size_t BH = (size_t)BATCH * NH;

        float4 pf = *(float4*)(stage + (0 * FBM + row) * FBNG + col4);
        float4 pi = *(float4*)(stage + (1 * FBM + row) * FBNG + col4);
        float4 pg = *(float4*)(stage + (2 * FBM + row) * FBNG + col4);
        float4 po = *(float4*)(stage + (3 * FBM + row) * FBNG + col4);
        float4 xf = *(const float4*)&g_xproj[((size_t)(0 * SEQ) + t) * BH + (size_t)m * NH + n];
        float4 xi = *(const float4*)&g_xproj[((size_t)(1 * SEQ) + t) * BH + (size_t)m * NH + n];
        float4 xg = *(const float4*)&g_xproj[((size_t)(2 * SEQ) + t) * BH + (size_t)m * NH + n];
        float4 xo = *(const float4*)&g_xproj[((size_t)(3 * SEQ) + t) * BH + (size_t)m * NH + n];
        float4 cv = *(const float4*)&g_c[(size_t)m * NH + n];

        float pfv[4]; float piv[4]; float pgv[4]; float pov[4];
        float xfv[4]; float xiv[4]; float xgv[4]; float xov[4];
        float ccv[4]; float hv[4]; float cn2[4];
        pfv[0]=pf.x; pfv[1]=pf.y; pfv[2]=pf.z; pfv[3]=pf.w;
        piv[0]=pi.x; piv[1]=pi.y; piv[2]=pi.z; piv[3]=pi.w;
        pgv[0]=pg.x; pgv[1]=pg.y; pgv[2]=pg.z; pgv[3]=pg.w;
        pov[0]=po.x; pov[1]=po.y; pov[2]=po.z; pov[3]=po.w;
        xfv[0]=xf.x; xfv[1]=xf.y; xfv[2]=xf.z; xfv[3]=xf.w;
        xiv[0]=xi.x; xiv[1]=xi.y; xiv[2]=xi.z; xiv[3]=xi.w;
        xgv[0]=xg.x; xgv[1]=xg.y; xgv[2]=xg.z; xgv[3]=xg.w;
        xov[0]=xo.x; xov[1]=xo.y; xov[2]=xo.z; xov[3]=xo.w;
        ccv[0]=cv.x; ccv[1]=cv.y; ccv[2]=cv.z; ccv[3]=cv.w;

        #pragma unroll
        for (int j = 0; j < 4; j++) {
            float fg = fast_sigmoid(pfv[j] + xfv[j]);
            float ig = fast_sigmoid(piv[j] + xiv[j]);
            float gg = fast_tanh(pgv[j] + xgv[j]);
            float og = fast_sigmoid(pov[j] + xov[j]);
            float c2 = fg * ccv[j] + ig * gg;
            cn2[j] = c2;
            hv[j] = og * fast_tanh(c2);
        }

        *(float4*)&g_c[(size_t)m * NH + n] = make_float4(cn2[0], cn2[1], cn2[2], cn2[3]);
        *(float4*)&g_h[(size_t)m * NH + n] = make_float4(hv[0], hv[1], hv[2], hv[3]);

        __nv_bfloat162* Hh = (__nv_bfloat162*)(hout_hi + (size_t)m * NH + n);
        __nv_bfloat162* Hl = (__nv_bfloat162*)(hout_lo + (size_t)m * NH + n);
        #pragma unroll
        for (int j = 0; j < 2; j++) {
            __nv_bfloat162 hh = __floats2bfloat162_rn(hv[2 * j], hv[2 * j + 1]);
            float l0 = hv[2 * j]     - __bfloat162float(__low2bfloat16(hh));
            float l1 = hv[2 * j + 1] - __bfloat162float(__high2bfloat16(hh));
            Hh[j] = hh;
            Hl[j] = __floats2bfloat162_rn(l0, l1);
        }
    }
}

// ---------------- bf16x3 input-projection GEMM (cp.async 3-stage) ----------------
__global__ __launch_bounds__(256) void proj_gemm(Ptr4 Bias)
{
    extern __shared__ __align__(16) unsigned char dynsm[];
    bf16* stg = (bf16*)dynsm;

    const int gate = blockIdx.z;
    const bf16* __restrict__ Bhi = g_Wx_hi + (size_t)gate * NH * NIN;
    const bf16* __restrict__ Blo = g_Wx_lo + (size_t)gate * NH * NIN;
    const float* __restrict__ bias = Bias.p[gate];

    const int tid   = threadIdx.x;
    const int warp  = tid >> 5;
    const int wm    = warp >> 2;
    const int wn    = warp & 3;
    const int mbase = blockIdx.y * BM;
    const int nbase = blockIdx.x * BN;

    // loader: 1024 16B-chunks per stage (4 planes x 64 rows x 4 chunks), 4/thread
    const bf16* gsrc[4];
    int soff[4];
    #pragma unroll
    for (int l = 0; l < 4; l++) {
        int idx = l * 256 + tid;
        int p   = idx >> 8;
        int w   = idx & 255;
        int row = w >> 2;
        int q   = (w & 3) * 8;
        soff[l] = (p * BM + row) * SKS + q;
        if (p == 0) {
            gsrc[l] = g_x_hi + (size_t)(mbase + row) * NIN + q;
        } else if (p == 1) {
            gsrc[l] = g_x_lo + (size_t)(mbase + row) * NIN + q;
        } else if (p == 2) {
            gsrc[l] = Bhi + (size_t)(nbase + row) * NIN + q;
        } else {
            gsrc[l] = Blo + (size_t)(nbase + row) * NIN + q;
        }
    }

    wmma::fragment<wmma::accumulator, 16, 16, 16, float> acc0;
    wmma::fragment<wmma::accumulator, 16, 16, 16, float> acc1;
    wmma::fill_fragment(acc0, 0.0f);
    wmma::fill_fragment(acc1, 0.0f);

    const int NC = NIN / BK;   // 16

    #pragma unroll
    for (int s = 0; s < PSTAGES - 1; s++) {
        const int ko = s * BK;
        #pragma unroll
        for (int l = 0; l < 4; l++) {
            __pipeline_memcpy_async(stg + s * PSTB + soff[l], gsrc[l] + ko, 16);
        }
        __pipeline_commit();
    }

    for (int c = 0; c < NC; c++) {
        __pipeline_wait_prior(PSTAGES - 2);
        __syncthreads();

        const int cn = c + PSTAGES - 1;
        if (cn < NC) {
            const int ko = cn * BK;
            const int ds = cn % PSTAGES;
            #pragma unroll
            for (int l = 0; l < 4; l++) {
                __pipeline_memcpy_async(stg + ds * PSTB + soff[l], gsrc[l] + ko, 16);
            }
        }
        __pipeline_commit();

        bf16* sp = stg + (c % PSTAGES) * PSTB;
        #pragma unroll
        for (int ks = 0; ks < 2; ks++) {
            wmma::fragment<wmma::matrix_b, 16, 16, 16, bf16, wmma::col_major> fbh;
            wmma::fragment<wmma::matrix_b, 16, 16, 16, bf16, wmma::col_major> fbl;
            wmma::load_matrix_sync(fbh, sp + (2 * BM + wn * 16) * SKS + ks * 16, SKS);
            wmma::load_matrix_sync(fbl, sp + (3 * BM + wn * 16) * SKS + ks * 16, SKS);

            wmma::fragment<wmma::matrix_a, 16, 16, 16, bf16, wmma::row_major> fah;
            wmma::fragment<wmma::matrix_a, 16, 16, 16, bf16, wmma::row_major> fal;
            wmma::load_matrix_sync(fah, sp + (0 * BM + wm * 32) * SKS + ks * 16, SKS);
            wmma::load_matrix_sync(fal, sp + (1 * BM + wm * 32) * SKS + ks * 16, SKS);
            wmma::mma_sync(acc0, fah, fbh, acc0);
            wmma::mma_sync(acc0, fah, fbl, acc0);
            wmma::mma_sync(acc0, fal, fbh, acc0);

            wmma::load_matrix_sync(fah, sp + (0 * BM + wm * 32 + 16) * SKS + ks * 16, SKS);
            wmma::load_matrix_sync(fal, sp + (1 * BM + wm * 32 + 16) * SKS + ks * 16, SKS);
            wmma::mma_sync(acc1, fah, fbh, acc1);
            wmma::mma_sync(acc1, fah, fbl, acc1);
            wmma::mma_sync(acc1, fal, fbh, acc1);
        }
    }

    __pipeline_wait_prior(0);
    __syncthreads();
    float* stage = (float*)dynsm;   // 64 x 64 floats
    wmma::store_matrix_sync(stage + (wm * 32) * 64 + wn * 16, acc0, 64, wmma::mem_row_major);
    wmma::store_matrix_sync(stage + (wm * 32 + 16) * 64 + wn * 16, acc1, 64, wmma::mem_row_major);
    __syncthreads();

    #pragma unroll
    for (int i = 0; i < 4; i++) {
        int e   = tid + i * 256;
        int row = e >> 4;
        int c4  = (e & 15) * 4;
        int m   = mbase + row;
        int bb  = m >> 8;
        int ss  = m & 255;
        int col = nbase + c4;
        float4 v = *(float4*)(stage + row * 64 + c4);
        v.x += bias[col + 0];
        v.y += bias[col + 1];
        v.z += bias[col + 2];
        v.w += bias[col + 3];
        *(float4*)&g_xproj[(((size_t)gate * SEQ + ss) * BATCH + bb) * NH + col] = v;
    }
}

// ---------------- fp32 output GEMM (small) ----------------
__global__ __launch_bounds__(256) void out_gemm(const float* __restrict__ Wy,
                                                const float* __restrict__ by,
                                                float* __restrict__ out)
{
    __shared__ float As[TK][SROW];
    __shared__ float Bs[TK][SROW];
    const int tid = threadIdx.x;
    const int tx = tid & 15;
    const int ty = tid >> 4;
    const int mbase = blockIdx.y * TM;
    const int nbase = blockIdx.x * TN;
    const int lm = tid >> 2;
    const int lk = (tid & 3) << 2;

    float acc[4][4];
    #pragma unroll
    for (int i = 0; i < 4; i++) {
        #pragma unroll
        for (int j = 0; j < 4; j++) { acc[i][j] = 0.f; }
    }

    for (int kt = 0; kt < NH; kt += TK) {
        float4 av = *(const float4*)&g_h[(size_t)(mbase + lm) * NH + kt + lk];
        float4 bv = *(const float4*)&Wy [(size_t)(nbase + lm) * NH + kt + lk];
        __syncthreads();
        As[lk + 0][lm] = av.x; As[lk + 1][lm] = av.y;
        As[lk + 2][lm] = av.z; As[lk + 3][lm] = av.w;
        Bs[lk + 0][lm] = bv.x; Bs[lk + 1][lm] = bv.y;
        Bs[lk + 2][lm] = bv.z; Bs[lk + 3][lm] = bv.w;
        __syncthreads();
        #pragma unroll
        for (int k = 0; k < TK; k++) {
            float ar[4]; float br[4];
            #pragma unroll
            for (int i = 0; i < 4; i++) { ar[i] = As[k][(ty << 2) + i]; }
            #pragma unroll
            for (int j = 0; j < 4; j++) { br[j] = Bs[k][(tx << 2) + j]; }
            #pragma unroll
            for (int i = 0; i < 4; i++) {
                #pragma unroll
                for (int j = 0; j < 4; j++) { acc[i][j] = fmaf(ar[i], br[j], acc[i][j]); }
            }
        }
    }

    #pragma unroll
    for (int i = 0; i < 4; i++) {
        int m = mbase + (ty << 2) + i;
        int n0 = nbase + (tx << 2);
        #pragma unroll
        for (int j = 0; j < 4; j++) {
            out[(size_t)m * NOUT + n0 + j] = acc[i][j] + by[n0 + j];
        }
    }
}

__global__ __launch_bounds__(256) void copy_hc(float* __restrict__ out)
{
    const int idx = blockIdx.x * 256 + threadIdx.x;  // grid 512
    out[(size_t)BATCH * NOUT + idx]                      = g_h[idx];
    out[(size_t)BATCH * NOUT + (size_t)BATCH * NH + idx] = g_c[idx];
}

// ---------------------------------------------------------------------------
extern "C" void kernel_launch(void* const* d_in, const int* in_sizes, int n_in,
                              void* d_out, int out_size)
{
    const float* x_seq = (const float*)d_in[0];
    Ptr4 Wx; Ptr4 Bx; Ptr4 Wh;
    Wx.p[0] = (const float*)d_in[1];  Bx.p[0] = (const float*)d_in[2];  Wh.p[0] = (const float*)d_in[3];
    Wx.p[1] = (const float*)d_in[4];  Bx.p[1] = (const float*)d_in[5];  Wh.p[1] = (const float*)d_in[6];
    Wx.p[2] = (const float*)d_in[7];  Bx.p[2] = (const float*)d_in[8];  Wh.p[2] = (const float*)d_in[9];
    Wx.p[3] = (const float*)d_in[10]; Bx.p[3] = (const float*)d_in[11]; Wh.p[3] = (const float*)d_in[12];
    const float* Why_w = (const float*)d_in[13];
    const float* Why_b = (const float*)d_in[14];
    float* out = (float*)d_out;

    const int rec_smem  = RSTAGES * RSTB * 2 + 4 * FBM * FBNG * 4;  // 61440 + 16384 = 77824
    const int proj_smem = PSTAGES * PSTB * 2;                       // 73728
    cudaFuncSetAttribute(rec_step,  cudaFuncAttributeMaxDynamicSharedMemorySize, rec_smem);
    cudaFuncSetAttribute(proj_gemm, cudaFuncAttributeMaxDynamicSharedMemorySize, proj_smem);

    init_state<<<512, 256>>>();

    split_wh<<<(4 * NH * NH) / 256, 256>>>(Wh);
    split_wx<<<(4 * NH * NIN) / 256, 256>>>(Wx);
    split_x<<<(BATCH * SEQ * NIN) / 256, 256>>>(x_seq);

    proj_gemm<<<dim3(NH / BN, (BATCH * SEQ) / BM, 4), 256, proj_smem>>>(Bx);

    for (int t = 0; t < SEQ; t++) {
        rec_step<<<dim3(NH / FBNG, BATCH / FBM), 256, rec_smem>>>(t);
    }

    out_gemm<<<dim3(NOUT / TN, BATCH / TM), 256>>>(Why_w, Why_b, out);
    copy_hc<<<512, 256>>>(out);
}

// round 9
// speedup vs baseline: 2.1191x; 1.0079x over previous
#include <cuda_runtime.h>
#include <cuda_bf16.h>
#include <mma.h>
#include <cuda_pipeline.h>

using namespace nvcuda;

#define BATCH 128
#define SEQ   256
#define NIN   512
#define NH    1024
#define NOUT  512

typedef __nv_bfloat16 bf16;

// proj GEMM tiling
#define BM 64
#define BN 64
#define BK 32
#define SKS 48
#define PSTAGES 3
#define PSTB (4 * BM * SKS)

// fused rec-step tiling: 64 m x (16 n per gate x 4 gates), K-tile 32, 512 threads
#define FBM 64
#define FBNG 16
#define FBK 32
#define FSK 40
#define RSTAGES 3
#define RROWS 256                      /* 2 A planes x 64 + 8 B planes x 16 */
#define RSTB (RROWS * FSK)             /* bf16 per rec stage = 10240 */
#define RTHREADS 512

// fp32 out_gemm tiling
#define TM 64
#define TN 64
#define TK 16
#define SROW 68

// ---------------- scratch (device globals) ----------------
__device__ float g_xproj[(size_t)4 * SEQ * BATCH * NH];
__device__ float g_h[BATCH * NH];
__device__ float g_c[BATCH * NH];
__device__ bf16  g_hA_hi[BATCH * NH];
__device__ bf16  g_hA_lo[BATCH * NH];
__device__ bf16  g_hB_hi[BATCH * NH];
__device__ bf16  g_hB_lo[BATCH * NH];
__device__ bf16  g_Wh_hi[(size_t)4 * NH * NH];
__device__ bf16  g_Wh_lo[(size_t)4 * NH * NH];
__device__ bf16  g_Wx_hi[(size_t)4 * NH * NIN];
__device__ bf16  g_Wx_lo[(size_t)4 * NH * NIN];
__device__ bf16  g_x_hi[(size_t)BATCH * SEQ * NIN];
__device__ bf16  g_x_lo[(size_t)BATCH * SEQ * NIN];

struct Ptr4 { const float* p[4]; };

__device__ __forceinline__ float fast_sigmoid(float x) { return 1.f / (1.f + __expf(-x)); }
__device__ __forceinline__ float fast_tanh(float x)    { return 2.f * fast_sigmoid(2.f * x) - 1.f; }

// ---------------- fused setup: init + all splits in ONE launch ----------------
// grid 65536 x 256 = 16,777,216 threads (size of x_seq)
__global__ __launch_bounds__(256) void fused_setup(const float* __restrict__ x,
                                                   Ptr4 Wh, Ptr4 Wx)
{
    const size_t idx = (size_t)blockIdx.x * 256 + threadIdx.x;

    // split_x: all 2^24 elements
    {
        float v = x[idx];
        bf16 hv = __float2bfloat16_rn(v);
        g_x_hi[idx] = hv;
        g_x_lo[idx] = __float2bfloat16_rn(v - __bfloat162float(hv));
    }
    // split_wh: first 4 * 2^20 threads
    if (idx < (size_t)4 * NH * NH) {
        int gate = (int)(idx >> 20);
        float v = Wh.p[gate][idx & ((1u << 20) - 1)];
        bf16 hv = __float2bfloat16_rn(v);
        g_Wh_hi[idx] = hv;
        g_Wh_lo[idx] = __float2bfloat16_rn(v - __bfloat162float(hv));
    }
    // split_wx: first 4 * 2^19 threads
    if (idx < (size_t)4 * NH * NIN) {
        int gate = (int)(idx >> 19);
        float v = Wx.p[gate][idx & ((1u << 19) - 1)];
        bf16 hv = __float2bfloat16_rn(v);
        g_Wx_hi[idx] = hv;
        g_Wx_lo[idx] = __float2bfloat16_rn(v - __bfloat162float(hv));
    }
    // init state: first BATCH*NH threads
    if (idx < (size_t)BATCH * NH) {
        g_h[idx] = 0.f;
        g_c[idx] = 0.f;
        g_hA_hi[idx] = __float2bfloat16_rn(0.f);
        g_hA_lo[idx] = __float2bfloat16_rn(0.f);
    }
}

// ---------------- fused recurrent step (512 threads, 16 warps) ----------------
// grid (NH/FBNG=64, BATCH/FBM=2) = 128 blocks.
// Stage rows: [0,64)=h hi, [64,128)=h lo, 128+p2*16 (p2=gate*2+isLo) = W planes.
// Warp (gp=warp>>2 gate, wq=warp&3 m-quarter) computes 16m x 16n for its gate.
__global__ __launch_bounds__(RTHREADS) void rec_step(int t)
{
    extern __shared__ __align__(16) unsigned char dynsm[];
    bf16*  stg   = (bf16*)dynsm;                                 // RSTAGES stages
    float* stage = (float*)(dynsm + (size_t)RSTAGES * RSTB * 2); // [4][64][16]

    const int par = t & 1;
    const bf16* __restrict__ hin_hi = par ? g_hB_hi : g_hA_hi;
    const bf16* __restrict__ hin_lo = par ? g_hB_lo : g_hA_lo;
    bf16* __restrict__ hout_hi = par ? g_hA_hi : g_hB_hi;
    bf16* __restrict__ hout_lo = par ? g_hA_lo : g_hB_lo;

    const int tid   = threadIdx.x;
    const int nbase = blockIdx.x * FBNG;
    const int mbase = blockIdx.y * FBM;

    // ---- epilogue operand prefetch (independent of the GEMM) ----
    const int erow  = tid >> 3;        // 0..63
    const int ecol2 = (tid & 7) * 2;   // 0..14
    const int em = mbase + erow;
    const int en = nbase + ecol2;
    const size_t BH = (size_t)BATCH * NH;
    float2 xf = *(const float2*)&g_xproj[((size_t)(0 * SEQ) + t) * BH + (size_t)em * NH + en];
    float2 xi = *(const float2*)&g_xproj[((size_t)(1 * SEQ) + t) * BH + (size_t)em * NH + en];
    float2 xg = *(const float2*)&g_xproj[((size_t)(2 * SEQ) + t) * BH + (size_t)em * NH + en];
    float2 xo = *(const float2*)&g_xproj[((size_t)(3 * SEQ) + t) * BH + (size_t)em * NH + en];
    float2 cv = *(const float2*)&g_c[(size_t)em * NH + en];

    // loader: 1024 16B-chunks per stage (256 rows x 4 chunks), 2 per thread
    const bf16* gsrc[2];
    int soff[2];
    #pragma unroll
    for (int l = 0; l < 2; l++) {
        int idx  = l * RTHREADS + tid;
        int row  = idx >> 2;          // 0..255
        int q    = (idx & 3) * 8;     // 0..24 bf16 (covers k 0..31)
        soff[l]  = row * FSK + q;
        if (row < 64) {
            gsrc[l] = hin_hi + (size_t)(mbase + row) * NH + q;
        } else if (row < 128) {
            gsrc[l] = hin_lo + (size_t)(mbase + row - 64) * NH + q;
        } else {
            int b    = row - 128;
            int p2   = b >> 4;        // 0..7
            int r    = b & 15;
            int gate = p2 >> 1;
            int islo = p2 & 1;
            const bf16* wbase = islo ? g_Wh_lo : g_Wh_hi;
            gsrc[l] = wbase + (size_t)gate * NH * NH + (size_t)(nbase + r) * NH + q;
        }
    }

    const int warp = tid >> 5;
    const int gp = warp >> 2;     // gate 0..3
    const int wq = warp & 3;      // m-quarter 0..3

    wmma::fragment<wmma::accumulator, 16, 16, 16, float> acc;
    wmma::fill_fragment(acc, 0.0f);

    const int NC = NH / FBK;   // 32

    #pragma unroll
    for (int s = 0; s < RSTAGES - 1; s++) {
        const int ko = s * FBK;
        #pragma unroll
        for (int l = 0; l < 2; l++) {
            __pipeline_memcpy_async(stg + s * RSTB + soff[l], gsrc[l] + ko, 16);
        }
        __pipeline_commit();
    }

    for (int c = 0; c < NC; c++) {
        __pipeline_wait_prior(RSTAGES - 2);
        __syncthreads();

        const int cn = c + RSTAGES - 1;
        if (cn < NC) {
            const int ko = cn * FBK;
            const int ds = cn % RSTAGES;
            #pragma unroll
            for (int l = 0; l < 2; l++) {
                __pipeline_memcpy_async(stg + ds * RSTB + soff[l], gsrc[l] + ko, 16);
            }
        }
        __pipeline_commit();

        bf16* sp = stg + (c % RSTAGES) * RSTB;
        #pragma unroll
        for (int ks = 0; ks < 2; ks++) {
            wmma::fragment<wmma::matrix_b, 16, 16, 16, bf16, wmma::col_major> fbh;
            wmma::fragment<wmma::matrix_b, 16, 16, 16, bf16, wmma::col_major> fbl;
            wmma::load_matrix_sync(fbh, sp + (128 + gp * 32) * FSK + ks * 16, FSK);
            wmma::load_matrix_sync(fbl, sp + (128 + gp * 32 + 16) * FSK + ks * 16, FSK);

            wmma::fragment<wmma::matrix_a, 16, 16, 16, bf16, wmma::row_major> fah;
            wmma::fragment<wmma::matrix_a, 16, 16, 16, bf16, wmma::row_major> fal;
            wmma::load_matrix_sync(fah, sp + (wq * 16) * FSK + ks * 16, FSK);
            wmma::load_matrix_sync(fal, sp + (64 + wq * 16) * FSK + ks * 16, FSK);

            wmma::mma_sync(acc, fah, fbh, acc);
            wmma::mma_sync(acc, fah, fbl, acc);
            wmma::mma_sync(acc, fal, fbh, acc);
        }
    }

    // stage pre-activations: stage[gate][m 0..63][n 0..15]
    wmma::store_matrix_sync(stage + ((gp * FBM) + (wq * 16)) * FBNG, acc, FBNG,
                            wmma::mem_row_major);
    __syncthreads();

    // cell update: 64m x 16n = 1024 cells, 2 consecutive n per thread
    {
        float2 pf = *(float2*)(stage + (0 * FBM + erow) * FBNG + ecol2);
        float2 pi = *(float2*)(stage + (1 * FBM + erow) * FBNG + ecol2);
        float2 pg = *(float2*)(stage + (2 * FBM + erow) * FBNG + ecol2);
        float2 po = *(float2*)(stage + (3 * FBM + erow) * FBNG + ecol2);

        float pfv[2]; float piv[2]; float pgv[2]; float pov[2];
        float xfv[2]; float xiv[2]; float xgv[2]; float xov[2];
        float ccv[2]; float hv[2]; float cn2[2];
        pfv[0]=pf.x; pfv[1]=pf.y;
        piv[0]=pi.x; piv[1]=pi.y;
        pgv[0]=pg.x; pgv[1]=pg.y;
        pov[0]=po.x; pov[1]=po.y;
        xfv[0]=xf.x; xfv[1]=xf.y;
        xiv[0]=xi.x; xiv[1]=xi.y;
        xgv[0]=xg.x; xgv[1]=xg.y;
        xov[0]=xo.x; xov[1]=xo.y;
        ccv[0]=cv.x; ccv[1]=cv.y;

        #pragma unroll
        for (int j = 0; j < 2; j++) {
            float fg = fast_sigmoid(pfv[j] + xfv[j]);
            float ig = fast_sigmoid(piv[j] + xiv[j]);
            float gg = fast_tanh(pgv[j] + xgv[j]);
            float og = fast_sigmoid(pov[j] + xov[j]);
            float c2 = fg * ccv[j] + ig * gg;
            cn2[j] = c2;
            hv[j] = og * fast_tanh(c2);
        }

        *(float2*)&g_c[(size_t)em * NH + en] = make_float2(cn2[0], cn2[1]);
        *(float2*)&g_h[(size_t)em * NH + en] = make_float2(hv[0], hv[1]);

        __nv_bfloat162 hh = __floats2bfloat162_rn(hv[0], hv[1]);
        float l0 = hv[0] - __bfloat162float(__low2bfloat16(hh));
        float l1 = hv[1] - __bfloat162float(__high2bfloat16(hh));
        *(__nv_bfloat162*)(hout_hi + (size_t)em * NH + en) = hh;
        *(__nv_bfloat162*)(hout_lo + (size_t)em * NH + en) = __floats2bfloat162_rn(l0, l1);
    }
}

// ---------------- bf16x3 input-projection GEMM (cp.async 3-stage) ----------------
__global__ __launch_bounds__(256) void proj_gemm(Ptr4 Bias)
{
    extern __shared__ __align__(16) unsigned char dynsm[];
    bf16* stg = (bf16*)dynsm;

    const int gate = blockIdx.z;
    const bf16* __restrict__ Bhi = g_Wx_hi + (size_t)gate * NH * NIN;
    const bf16* __restrict__ Blo = g_Wx_lo + (size_t)gate * NH * NIN;
    const float* __restrict__ bias = Bias.p[gate];

    const int tid   = threadIdx.x;
    const int warp  = tid >> 5;
    const int wm    = warp >> 2;
    const int wn    = warp & 3;
    const int mbase = blockIdx.y * BM;
    const int nbase = blockIdx.x * BN;

    const bf16* gsrc[4];
    int soff[4];
    #pragma unroll
    for (int l = 0; l < 4; l++) {
        int idx = l * 256 + tid;
        int p   = idx >> 8;
        int w   = idx & 255;
        int row = w >> 2;
        int q   = (w & 3) * 8;
        soff[l] = (p * BM + row) * SKS + q;
        if (p == 0) {
            gsrc[l] = g_x_hi + (size_t)(mbase + row) * NIN + q;
        } else if (p == 1) {
            gsrc[l] = g_x_lo + (size_t)(mbase + row) * NIN + q;
        } else if (p == 2) {
            gsrc[l] = Bhi + (size_t)(nbase + row) * NIN + q;
        } else {
            gsrc[l] = Blo + (size_t)(nbase + row) * NIN + q;
        }
    }

    wmma::fragment<wmma::accumulator, 16, 16, 16, float> acc0;
    wmma::fragment<wmma::accumulator, 16, 16, 16, float> acc1;
    wmma::fill_fragment(acc0, 0.0f);
    wmma::fill_fragment(acc1, 0.0f);

    const int NC = NIN / BK;   // 16

    #pragma unroll
    for (int s = 0; s < PSTAGES - 1; s++) {
        const int ko = s * BK;
        #pragma unroll
        for (int l = 0; l < 4; l++) {
            __pipeline_memcpy_async(stg + s * PSTB + soff[l], gsrc[l] + ko, 16);
        }
        __pipeline_commit();
    }

    for (int c = 0; c < NC; c++) {
        __pipeline_wait_prior(PSTAGES - 2);
        __syncthreads();

        const int cn = c + PSTAGES - 1;
        if (cn < NC) {
            const int ko = cn * BK;
            const int ds = cn % PSTAGES;
            #pragma unroll
            for (int l = 0; l < 4; l++) {
                __pipeline_memcpy_async(stg + ds * PSTB + soff[l], gsrc[l] + ko, 16);
            }
        }
        __pipeline_commit();

        bf16* sp = stg + (c % PSTAGES) * PSTB;
        #pragma unroll
        for (int ks = 0; ks < 2; ks++) {
            wmma::fragment<wmma::matrix_b, 16, 16, 16, bf16, wmma::col_major> fbh;
            wmma::fragment<wmma::matrix_b, 16, 16, 16, bf16, wmma::col_major> fbl;
            wmma::load_matrix_sync(fbh, sp + (2 * BM + wn * 16) * SKS + ks * 16, SKS);
            wmma::load_matrix_sync(fbl, sp + (3 * BM + wn * 16) * SKS + ks * 16, SKS);

            wmma::fragment<wmma::matrix_a, 16, 16, 16, bf16, wmma::row_major> fah;
            wmma::fragment<wmma::matrix_a, 16, 16, 16, bf16, wmma::row_major> fal;
            wmma::load_matrix_sync(fah, sp + (0 * BM + wm * 32) * SKS + ks * 16, SKS);
            wmma::load_matrix_sync(fal, sp + (1 * BM + wm * 32) * SKS + ks * 16, SKS);
            wmma::mma_sync(acc0, fah, fbh, acc0);
            wmma::mma_sync(acc0, fah, fbl, acc0);
            wmma::mma_sync(acc0, fal, fbh, acc0);

            wmma::load_matrix_sync(fah, sp + (0 * BM + wm * 32 + 16) * SKS + ks * 16, SKS);
            wmma::load_matrix_sync(fal, sp + (1 * BM + wm * 32 + 16) * SKS + ks * 16, SKS);
            wmma::mma_sync(acc1, fah, fbh, acc1);
            wmma::mma_sync(acc1, fah, fbl, acc1);
            wmma::mma_sync(acc1, fal, fbh, acc1);
        }
    }

    __pipeline_wait_prior(0);
    __syncthreads();
    float* stage = (float*)dynsm;   // 64 x 64 floats
    wmma::store_matrix_sync(stage + (wm * 32) * 64 + wn * 16, acc0, 64, wmma::mem_row_major);
    wmma::store_matrix_sync(stage + (wm * 32 + 16) * 64 + wn * 16, acc1, 64, wmma::mem_row_major);
    __syncthreads();

    #pragma unroll
    for (int i = 0; i < 4; i++) {
        int e   = tid + i * 256;
        int row = e >> 4;
        int c4  = (e & 15) * 4;
        int m   = mbase + row;
        int bb  = m >> 8;
        int ss  = m & 255;
        int col = nbase + c4;
        float4 v = *(float4*)(stage + row * 64 + c4);
        v.x += bias[col + 0];
        v.y += bias[col + 1];
        v.z += bias[col + 2];
        v.w += bias[col + 3];
        *(float4*)&g_xproj[(((size_t)gate * SEQ + ss) * BATCH + bb) * NH + col] = v;
    }
}

// ---------------- fp32 output GEMM (small) ----------------
__global__ __launch_bounds__(256) void out_gemm(const float* __restrict__ Wy,
                                                const float* __restrict__ by,
                                                float* __restrict__ out)
{
    __shared__ float As[TK][SROW];
    __shared__ float Bs[TK][SROW];
    const int tid = threadIdx.x;
    const int tx = tid & 15;
    const int ty = tid >> 4;
    const int mbase = blockIdx.y * TM;
    const int nbase = blockIdx.x * TN;
    const int lm = tid >> 2;
    const int lk = (tid & 3) << 2;

    float acc[4][4];
    #pragma unroll
    for (int i = 0; i < 4; i++) {
        #pragma unroll
        for (int j = 0; j < 4; j++) { acc[i][j] = 0.f; }
    }

    for (int kt = 0; kt < NH; kt += TK) {
        float4 av = *(const float4*)&g_h[(size_t)(mbase + lm) * NH + kt + lk];
        float4 bv = *(const float4*)&Wy [(size_t)(nbase + lm) * NH + kt + lk];
        __syncthreads();
        As[lk + 0][lm] = av.x; As[lk + 1][lm] = av.y;
        As[lk + 2][lm] = av.z; As[lk + 3][lm] = av.w;
        Bs[lk + 0][lm] = bv.x; Bs[lk + 1][lm] = bv.y;
        Bs[lk + 2][lm] = bv.z; Bs[lk + 3][lm] = bv.w;
        __syncthreads();
        #pragma unroll
        for (int k = 0; k < TK; k++) {
            float ar[4]; float br[4];
            #pragma unroll
            for (int i = 0; i < 4; i++) { ar[i] = As[k][(ty << 2) + i]; }
            #pragma unroll
            for (int j = 0; j < 4; j++) { br[j] = Bs[k][(tx << 2) + j]; }
            #pragma unroll
            for (int i = 0; i < 4; i++) {
                #pragma unroll
                for (int j = 0; j < 4; j++) { acc[i][j] = fmaf(ar[i], br[j], acc[i][j]); }
            }
        }
    }

    #pragma unroll
    for (int i = 0; i < 4; i++) {
        int m = mbase + (ty << 2) + i;
        int n0 = nbase + (tx << 2);
        #pragma unroll
        for (int j = 0; j < 4; j++) {
            out[(size_t)m * NOUT + n0 + j] = acc[i][j] + by[n0 + j];
        }
    }
}

__global__ __launch_bounds__(256) void copy_hc(float* __restrict__ out)
{
    const int idx = blockIdx.x * 256 + threadIdx.x;  // grid 512
    out[(size_t)BATCH * NOUT + idx]                      = g_h[idx];
    out[(size_t)BATCH * NOUT + (size_t)BATCH * NH + idx] = g_c[idx];
}

// ---------------------------------------------------------------------------
extern "C" void kernel_launch(void* const* d_in, const int* in_sizes, int n_in,
                              void* d_out, int out_size)
{
    const float* x_seq = (const float*)d_in[0];
    Ptr4 Wx; Ptr4 Bx; Ptr4 Wh;
    Wx.p[0] = (const float*)d_in[1];  Bx.p[0] = (const float*)d_in[2];  Wh.p[0] = (const float*)d_in[3];
    Wx.p[1] = (const float*)d_in[4];  Bx.p[1] = (const float*)d_in[5];  Wh.p[1] = (const float*)d_in[6];
    Wx.p[2] = (const float*)d_in[7];  Bx.p[2] = (const float*)d_in[8];  Wh.p[2] = (const float*)d_in[9];
    Wx.p[3] = (const float*)d_in[10]; Bx.p[3] = (const float*)d_in[11]; Wh.p[3] = (const float*)d_in[12];
    const float* Why_w = (const float*)d_in[13];
    const float* Why_b = (const float*)d_in[14];
    float* out = (float*)d_out;

    const int rec_smem  = RSTAGES * RSTB * 2 + 4 * FBM * FBNG * 4;  // 77824
    const int proj_smem = PSTAGES * PSTB * 2;                       // 73728
    cudaFuncSetAttribute(rec_step,  cudaFuncAttributeMaxDynamicSharedMemorySize, rec_smem);
    cudaFuncSetAttribute(proj_gemm, cudaFuncAttributeMaxDynamicSharedMemorySize, proj_smem);

    fused_setup<<<65536, 256>>>(x_seq, Wh, Wx);

    proj_gemm<<<dim3(NH / BN, (BATCH * SEQ) / BM, 4), 256, proj_smem>>>(Bx);

    for (int t = 0; t < SEQ; t++) {
        rec_step<<<dim3(NH / FBNG, BATCH / FBM), RTHREADS, rec_smem>>>(t);
    }

    out_gemm<<<dim3(NOUT / TN, BATCH / TM), 256>>>(Why_w, Why_b, out);
    copy_hc<<<512, 256>>>(out);
}